// round 13
// baseline (speedup 1.0000x reference)
#include <cuda_runtime.h>
#include <cuda_bf16.h>
#include <cstdint>

#define INV_SQRT3 0.57735026918962576451f
#define INV_SQRT2 0.70710678118654752440f
#define LN_EPS 1e-5f

#define MAX_NODES 16384
#define MAX_EDGES 131072
#define BUCKET_CAP 64   // max degree ~27 for Poisson(8) over 16K bins; 64 is >>10 sigma

// scratch (allocation-free rule: __device__ globals; statically zero-initialized)
__device__ int  g_hist[MAX_NODES];                     // ALWAYS zero at kernel_launch entry
__device__ int2 g_bucket[MAX_NODES * BUCKET_CAP];      // (edge_id, src_node) per dst bucket

__device__ __forceinline__ float warp_sum(float v) {
    v += __shfl_xor_sync(0xffffffffu, v, 16);
    v += __shfl_xor_sync(0xffffffffu, v, 8);
    v += __shfl_xor_sync(0xffffffffu, v, 4);
    v += __shfl_xor_sync(0xffffffffu, v, 2);
    v += __shfl_xor_sync(0xffffffffu, v, 1);
    return v;
}

// ---------------------------------------------------------------------------
// Single-pass bucketing: rank via atomicAdd, direct scatter into fixed-stride
// per-node buckets. Replaces hist+scan+scatter.
// ---------------------------------------------------------------------------
__global__ void bucket_kernel(const int* __restrict__ edge_dst,
                              const int* __restrict__ edge_src,
                              int n_edges) {
    int i2 = (blockIdx.x * blockDim.x + threadIdx.x) * 2;
    if (i2 + 1 < n_edges) {
        const int2 d = *reinterpret_cast<const int2*>(edge_dst + i2);
        const int2 s = *reinterpret_cast<const int2*>(edge_src + i2);
        const int r0 = atomicAdd(&g_hist[d.x], 1);
        const int r1 = atomicAdd(&g_hist[d.y], 1);
        if (r0 < BUCKET_CAP) g_bucket[d.x * BUCKET_CAP + r0] = make_int2(i2 + 0, s.x);
        if (r1 < BUCKET_CAP) g_bucket[d.y * BUCKET_CAP + r1] = make_int2(i2 + 1, s.y);
    } else if (i2 < n_edges) {
        const int dd = edge_dst[i2];
        const int r = atomicAdd(&g_hist[dd], 1);
        if (r < BUCKET_CAP) g_bucket[dd * BUCKET_CAP + r] = make_int2(i2, edge_src[i2]);
    }
}

// ---------------------------------------------------------------------------
// Fused gather + depthwise TP + bias + equivariant LN.
// TWO warps per node, split by CHANNEL GROUP (independent after deg read):
//   sub 0 (scalar path): xs,w0,w1  -> fields 0 (out0a), 2 (out1a)
//   sub 1 (vector path): xv,w2..w4 -> fields 1, 3, 4
// Both warps read deg = g_hist[node]; a per-node-pair named barrier orders
// those reads before sub0/lane0 re-zeroes g_hist[node] (restores invariant).
// 2-edge unroll, 64-reg cap -> 4 blocks/SM. edge_weight via __ldcs, out via __stcs.
// ---------------------------------------------------------------------------
__global__ void __launch_bounds__(256, 4) fused_tp_ln_kernel(
    const float* __restrict__ node_feat,   // (N, 320)
    const float* __restrict__ edge_sh,     // (E, 4)
    const float* __restrict__ edge_weight, // (E, 448)
    const float* __restrict__ tp_bias,     // (192,)
    const float* __restrict__ lnw,         // (448,)
    const float* __restrict__ lnb,         // (192,)
    float*       __restrict__ out,         // (N, 960)
    int n_nodes)
{
    const int warpInBlock = threadIdx.x >> 5;   // 0..7
    const int lane = threadIdx.x & 31;
    const int node = blockIdx.x * 4 + (warpInBlock >> 1);
    const int sub  = warpInBlock & 1;
    if (node >= n_nodes) return;

    int deg = g_hist[node];
    // order both warps' deg reads before the re-zero (per-node-pair barrier)
    asm volatile("bar.sync %0, 64;" :: "r"((warpInBlock >> 1) + 1) : "memory");
    if (sub == 0 && lane == 0) g_hist[node] = 0;
    if (deg > BUCKET_CAP) deg = BUCKET_CAP;

    const float fdeg = (float)deg;
    const int2* bucket = g_bucket + (size_t)node * BUCKET_CAP;
    float* row = out + (size_t)node * 960u;

    if (sub == 0) {
        // ================= scalar path: out0a (4) + out1a (12) ================
        float a0 = 0.f, a1 = 0.f, a2 = 0.f, a3 = 0.f;
        float A[12];
#pragma unroll
        for (int i = 0; i < 12; i++) A[i] = 0.f;

        int ei = 0;
        for (; ei + 1 < deg; ei += 2) {
            const int2 es0 = __ldg(bucket + ei);
            const int2 es1 = __ldg(bucket + ei + 1);

            const float4 sh0 = __ldg(reinterpret_cast<const float4*>(edge_sh) + es0.x);
            const float4 sh1 = __ldg(reinterpret_cast<const float4*>(edge_sh) + es1.x);
            const float4 xs0 = __ldg(reinterpret_cast<const float4*>(node_feat + (size_t)es0.y * 320u) + lane);
            const float4 xs1 = __ldg(reinterpret_cast<const float4*>(node_feat + (size_t)es1.y * 320u) + lane);
            const float* wr0 = edge_weight + (size_t)es0.x * 448u;
            const float* wr1 = edge_weight + (size_t)es1.x * 448u;
            const float4 w00 = __ldcs(reinterpret_cast<const float4*>(wr0) + lane);
            const float4 w01 = __ldcs(reinterpret_cast<const float4*>(wr1) + lane);
            const float4 w10 = __ldcs(reinterpret_cast<const float4*>(wr0 + 128) + lane);
            const float4 w11 = __ldcs(reinterpret_cast<const float4*>(wr1 + 128) + lane);

            {
                const float ys = sh0.x;
                a0 += w00.x * xs0.x * ys; a1 += w00.y * xs0.y * ys;
                a2 += w00.z * xs0.z * ys; a3 += w00.w * xs0.w * ys;
                const float t0 = w10.x * xs0.x, t1 = w10.y * xs0.y;
                const float t2 = w10.z * xs0.z, t3 = w10.w * xs0.w;
                A[0] += t0 * sh0.y; A[1]  += t0 * sh0.z; A[2]  += t0 * sh0.w;
                A[3] += t1 * sh0.y; A[4]  += t1 * sh0.z; A[5]  += t1 * sh0.w;
                A[6] += t2 * sh0.y; A[7]  += t2 * sh0.z; A[8]  += t2 * sh0.w;
                A[9] += t3 * sh0.y; A[10] += t3 * sh0.z; A[11] += t3 * sh0.w;
            }
            {
                const float ys = sh1.x;
                a0 += w01.x * xs1.x * ys; a1 += w01.y * xs1.y * ys;
                a2 += w01.z * xs1.z * ys; a3 += w01.w * xs1.w * ys;
                const float t0 = w11.x * xs1.x, t1 = w11.y * xs1.y;
                const float t2 = w11.z * xs1.z, t3 = w11.w * xs1.w;
                A[0] += t0 * sh1.y; A[1]  += t0 * sh1.z; A[2]  += t0 * sh1.w;
                A[3] += t1 * sh1.y; A[4]  += t1 * sh1.z; A[5]  += t1 * sh1.w;
                A[6] += t2 * sh1.y; A[7]  += t2 * sh1.z; A[8]  += t2 * sh1.w;
                A[9] += t3 * sh1.y; A[10] += t3 * sh1.z; A[11] += t3 * sh1.w;
            }
        }
        if (ei < deg) {
            const int2 es0 = __ldg(bucket + ei);
            const float4 sh0 = __ldg(reinterpret_cast<const float4*>(edge_sh) + es0.x);
            const float4 xs0 = __ldg(reinterpret_cast<const float4*>(node_feat + (size_t)es0.y * 320u) + lane);
            const float* wr0 = edge_weight + (size_t)es0.x * 448u;
            const float4 w00 = __ldcs(reinterpret_cast<const float4*>(wr0) + lane);
            const float4 w10 = __ldcs(reinterpret_cast<const float4*>(wr0 + 128) + lane);
            const float ys = sh0.x;
            a0 += w00.x * xs0.x * ys; a1 += w00.y * xs0.y * ys;
            a2 += w00.z * xs0.z * ys; a3 += w00.w * xs0.w * ys;
            const float t0 = w10.x * xs0.x, t1 = w10.y * xs0.y;
            const float t2 = w10.z * xs0.z, t3 = w10.w * xs0.w;
            A[0] += t0 * sh0.y; A[1]  += t0 * sh0.z; A[2]  += t0 * sh0.w;
            A[3] += t1 * sh0.y; A[4]  += t1 * sh0.z; A[5]  += t1 * sh0.w;
            A[6] += t2 * sh0.y; A[7]  += t2 * sh0.z; A[8]  += t2 * sh0.w;
            A[9] += t3 * sh0.y; A[10] += t3 * sh0.z; A[11] += t3 * sh0.w;
        }

        const float4 b0 = __ldg(reinterpret_cast<const float4*>(tp_bias) + lane);
        a0 += fdeg * b0.x; a1 += fdeg * b0.y; a2 += fdeg * b0.z; a3 += fdeg * b0.w;

        float s0 = a0 + a1 + a2 + a3;
        float q0 = a0 * a0 + a1 * a1 + a2 * a2 + a3 * a3;
        float q2 = 0.f;
#pragma unroll
        for (int i = 0; i < 12; i++) q2 += A[i] * A[i];
        s0 = warp_sum(s0); q0 = warp_sum(q0); q2 = warp_sum(q2);

        const float mu0 = s0 * (1.f / 128.f);
        const float r0  = rsqrtf(fmaxf(q0 * (1.f / 128.f) - mu0 * mu0, 0.f) + LN_EPS);
        const float r2  = rsqrtf(q2 * (1.f / 384.f) + LN_EPS);

        {   // field0
            const float4 wv = __ldg(reinterpret_cast<const float4*>(lnw) + lane);
            const float4 bv = __ldg(reinterpret_cast<const float4*>(lnb) + lane);
            float4 o;
            o.x = (a0 - mu0) * r0 * wv.x + bv.x;
            o.y = (a1 - mu0) * r0 * wv.y + bv.y;
            o.z = (a2 - mu0) * r0 * wv.z + bv.z;
            o.w = (a3 - mu0) * r0 * wv.w + bv.w;
            __stcs(reinterpret_cast<float4*>(row + 4 * lane), o);
        }
        {   // field2: channels u = 4*lane + {0..3}
            const float4 wv = __ldg(reinterpret_cast<const float4*>(lnw + 192) + lane);
            const float sa = wv.x * r2, sb = wv.y * r2, sc = wv.z * r2, sd = wv.w * r2;
            __stcs(reinterpret_cast<float4*>(row + 192 + 12 * lane),
                   make_float4(A[0] * sa, A[1] * sa, A[2]  * sa, A[3]  * sb));
            __stcs(reinterpret_cast<float4*>(row + 192 + 12 * lane + 4),
                   make_float4(A[4] * sb, A[5] * sb, A[6]  * sc, A[7]  * sc));
            __stcs(reinterpret_cast<float4*>(row + 192 + 12 * lane + 8),
                   make_float4(A[8] * sc, A[9] * sd, A[10] * sd, A[11] * sd));
        }
    } else {
        // ============ vector path: out0b (2) + out1b (6) + out1c (6) ==========
        float ob0 = 0.f, ob1 = 0.f;
        float B[6], C[6];
#pragma unroll
        for (int i = 0; i < 6; i++) { B[i] = 0.f; C[i] = 0.f; }

        int ei = 0;
        for (; ei + 1 < deg; ei += 2) {
            const int2 es0 = __ldg(bucket + ei);
            const int2 es1 = __ldg(bucket + ei + 1);

            const float4 sh0 = __ldg(reinterpret_cast<const float4*>(edge_sh) + es0.x);
            const float4 sh1 = __ldg(reinterpret_cast<const float4*>(edge_sh) + es1.x);
            const float* xr0 = node_feat + (size_t)es0.y * 320u + 128u;
            const float* xr1 = node_feat + (size_t)es1.y * 320u + 128u;
            const float* wr0 = edge_weight + (size_t)es0.x * 448u;
            const float* wr1 = edge_weight + (size_t)es1.x * 448u;

            const float2 w20 = __ldcs(reinterpret_cast<const float2*>(wr0 + 256) + lane);
            const float2 w30 = __ldcs(reinterpret_cast<const float2*>(wr0 + 320) + lane);
            const float2 w40 = __ldcs(reinterpret_cast<const float2*>(wr0 + 384) + lane);
            const float2 p00 = __ldg(reinterpret_cast<const float2*>(xr0 + 6 * lane));
            const float2 p10 = __ldg(reinterpret_cast<const float2*>(xr0 + 6 * lane + 2));
            const float2 p20 = __ldg(reinterpret_cast<const float2*>(xr0 + 6 * lane + 4));

            const float2 w21 = __ldcs(reinterpret_cast<const float2*>(wr1 + 256) + lane);
            const float2 w31 = __ldcs(reinterpret_cast<const float2*>(wr1 + 320) + lane);
            const float2 w41 = __ldcs(reinterpret_cast<const float2*>(wr1 + 384) + lane);
            const float2 p01 = __ldg(reinterpret_cast<const float2*>(xr1 + 6 * lane));
            const float2 p11 = __ldg(reinterpret_cast<const float2*>(xr1 + 6 * lane + 2));
            const float2 p21 = __ldg(reinterpret_cast<const float2*>(xr1 + 6 * lane + 4));

            {
                const float ys = sh0.x, yv0 = sh0.y, yv1 = sh0.z, yv2 = sh0.w;
                const float d0 = p00.x * yv0 + p00.y * yv1 + p10.x * yv2;
                const float d1 = p10.y * yv0 + p20.x * yv1 + p20.y * yv2;
                ob0 += w30.x * d0 * INV_SQRT3;
                ob1 += w30.y * d1 * INV_SQRT3;
                const float c0 = w20.x * ys, c1 = w20.y * ys;
                B[0] += c0 * p00.x; B[1] += c0 * p00.y; B[2] += c0 * p10.x;
                B[3] += c1 * p10.y; B[4] += c1 * p20.x; B[5] += c1 * p20.y;
                const float k0 = w40.x * INV_SQRT2, k1 = w40.y * INV_SQRT2;
                C[0] += k0 * (p00.y * yv2 - p10.x * yv1);
                C[1] += k0 * (p10.x * yv0 - p00.x * yv2);
                C[2] += k0 * (p00.x * yv1 - p00.y * yv0);
                C[3] += k1 * (p20.x * yv2 - p20.y * yv1);
                C[4] += k1 * (p20.y * yv0 - p10.y * yv2);
                C[5] += k1 * (p10.y * yv1 - p20.x * yv0);
            }
            {
                const float ys = sh1.x, yv0 = sh1.y, yv1 = sh1.z, yv2 = sh1.w;
                const float d0 = p01.x * yv0 + p01.y * yv1 + p11.x * yv2;
                const float d1 = p11.y * yv0 + p21.x * yv1 + p21.y * yv2;
                ob0 += w31.x * d0 * INV_SQRT3;
                ob1 += w31.y * d1 * INV_SQRT3;
                const float c0 = w21.x * ys, c1 = w21.y * ys;
                B[0] += c0 * p01.x; B[1] += c0 * p01.y; B[2] += c0 * p11.x;
                B[3] += c1 * p11.y; B[4] += c1 * p21.x; B[5] += c1 * p21.y;
                const float k0 = w41.x * INV_SQRT2, k1 = w41.y * INV_SQRT2;
                C[0] += k0 * (p01.y * yv2 - p11.x * yv1);
                C[1] += k0 * (p11.x * yv0 - p01.x * yv2);
                C[2] += k0 * (p01.x * yv1 - p01.y * yv0);
                C[3] += k1 * (p21.x * yv2 - p21.y * yv1);
                C[4] += k1 * (p21.y * yv0 - p11.y * yv2);
                C[5] += k1 * (p11.y * yv1 - p21.x * yv0);
            }
        }
        if (ei < deg) {
            const int2 es0 = __ldg(bucket + ei);
            const float4 sh0 = __ldg(reinterpret_cast<const float4*>(edge_sh) + es0.x);
            const float* xr0 = node_feat + (size_t)es0.y * 320u + 128u;
            const float* wr0 = edge_weight + (size_t)es0.x * 448u;
            const float2 w20 = __ldcs(reinterpret_cast<const float2*>(wr0 + 256) + lane);
            const float2 w30 = __ldcs(reinterpret_cast<const float2*>(wr0 + 320) + lane);
            const float2 w40 = __ldcs(reinterpret_cast<const float2*>(wr0 + 384) + lane);
            const float2 p00 = __ldg(reinterpret_cast<const float2*>(xr0 + 6 * lane));
            const float2 p10 = __ldg(reinterpret_cast<const float2*>(xr0 + 6 * lane + 2));
            const float2 p20 = __ldg(reinterpret_cast<const float2*>(xr0 + 6 * lane + 4));
            const float ys = sh0.x, yv0 = sh0.y, yv1 = sh0.z, yv2 = sh0.w;
            const float d0 = p00.x * yv0 + p00.y * yv1 + p10.x * yv2;
            const float d1 = p10.y * yv0 + p20.x * yv1 + p20.y * yv2;
            ob0 += w30.x * d0 * INV_SQRT3;
            ob1 += w30.y * d1 * INV_SQRT3;
            const float c0 = w20.x * ys, c1 = w20.y * ys;
            B[0] += c0 * p00.x; B[1] += c0 * p00.y; B[2] += c0 * p10.x;
            B[3] += c1 * p10.y; B[4] += c1 * p20.x; B[5] += c1 * p20.y;
            const float k0 = w40.x * INV_SQRT2, k1 = w40.y * INV_SQRT2;
            C[0] += k0 * (p00.y * yv2 - p10.x * yv1);
            C[1] += k0 * (p10.x * yv0 - p00.x * yv2);
            C[2] += k0 * (p00.x * yv1 - p00.y * yv0);
            C[3] += k1 * (p20.x * yv2 - p20.y * yv1);
            C[4] += k1 * (p20.y * yv0 - p10.y * yv2);
            C[5] += k1 * (p10.y * yv1 - p20.x * yv0);
        }

        const float2 bb = __ldg(reinterpret_cast<const float2*>(tp_bias + 128) + lane);
        ob0 += fdeg * bb.x; ob1 += fdeg * bb.y;

        float s1 = ob0 + ob1;
        float q1 = ob0 * ob0 + ob1 * ob1;
        float q3 = 0.f, q4 = 0.f;
#pragma unroll
        for (int i = 0; i < 6; i++) { q3 += B[i] * B[i]; q4 += C[i] * C[i]; }
        s1 = warp_sum(s1); q1 = warp_sum(q1);
        q3 = warp_sum(q3); q4 = warp_sum(q4);

        const float mu1 = s1 * (1.f / 64.f);
        const float r1  = rsqrtf(fmaxf(q1 * (1.f / 64.f) - mu1 * mu1, 0.f) + LN_EPS);
        const float r3  = rsqrtf(q3 * (1.f / 192.f) + LN_EPS);
        const float r4  = rsqrtf(q4 * (1.f / 192.f) + LN_EPS);

        {   // field1
            const float2 wv = __ldg(reinterpret_cast<const float2*>(lnw + 128) + lane);
            const float2 bv = __ldg(reinterpret_cast<const float2*>(lnb + 128) + lane);
            float2 o;
            o.x = (ob0 - mu1) * r1 * wv.x + bv.x;
            o.y = (ob1 - mu1) * r1 * wv.y + bv.y;
            __stcs(reinterpret_cast<float2*>(row + 128 + 2 * lane), o);
        }
        {   // field3
            const float2 wv = __ldg(reinterpret_cast<const float2*>(lnw + 320) + lane);
            const float sa = wv.x * r3, sb = wv.y * r3;
            __stcs(reinterpret_cast<float2*>(row + 576 + 6 * lane),     make_float2(B[0] * sa, B[1] * sa));
            __stcs(reinterpret_cast<float2*>(row + 576 + 6 * lane + 2), make_float2(B[2] * sa, B[3] * sb));
            __stcs(reinterpret_cast<float2*>(row + 576 + 6 * lane + 4), make_float2(B[4] * sb, B[5] * sb));
        }
        {   // field4
            const float2 wv = __ldg(reinterpret_cast<const float2*>(lnw + 384) + lane);
            const float sa = wv.x * r4, sb = wv.y * r4;
            __stcs(reinterpret_cast<float2*>(row + 768 + 6 * lane),     make_float2(C[0] * sa, C[1] * sa));
            __stcs(reinterpret_cast<float2*>(row + 768 + 6 * lane + 2), make_float2(C[2] * sa, C[3] * sb));
            __stcs(reinterpret_cast<float2*>(row + 768 + 6 * lane + 4), make_float2(C[4] * sb, C[5] * sb));
        }
    }
}

// ---------------------------------------------------------------------------
extern "C" void kernel_launch(void* const* d_in, const int* in_sizes, int n_in,
                              void* d_out, int out_size)
{
    const float* node_feat   = (const float*)d_in[0];
    const float* edge_sh     = (const float*)d_in[1];
    const float* edge_weight = (const float*)d_in[2];
    const float* tp_bias     = (const float*)d_in[3];
    const float* ln_weight   = (const float*)d_in[4];
    const float* ln_bias     = (const float*)d_in[5];
    const int*   edge_src    = (const int*)d_in[6];
    const int*   edge_dst    = (const int*)d_in[7];
    float* out = (float*)d_out;

    const int n_nodes = in_sizes[0] / 320;
    const int n_edges = in_sizes[7];

    // single-pass bucketing (replaces hist+scan+scatter)
    {
        const int threads = (n_edges + 1) / 2;
        bucket_kernel<<<(threads + 255) / 256, 256>>>(edge_dst, edge_src, n_edges);
    }

    // 2 warps per node (channel-split), 4 nodes per 256-thread block.
    // fused kernel also re-zeroes g_hist (restores the entry invariant).
    const int blocks = (n_nodes + 3) / 4;
    fused_tp_ln_kernel<<<blocks, 256>>>(node_feat, edge_sh, edge_weight,
                                        tp_bias, ln_weight, ln_bias,
                                        out, n_nodes);
}

// round 14
// speedup vs baseline: 1.4133x; 1.4133x over previous
#include <cuda_runtime.h>
#include <cuda_bf16.h>
#include <cstdint>

#define INV_SQRT3 0.57735026918962576451f
#define INV_SQRT2 0.70710678118654752440f
#define LN_EPS 1e-5f

#define MAX_NODES 16384
#define MAX_EDGES 131072
#define BUCKET_CAP 64   // max degree ~27 for Poisson(8); 64 is >>10 sigma

// scratch (allocation-free rule: __device__ globals; statically zero-initialized)
__device__ int  g_hist[MAX_NODES];                     // ALWAYS zero at kernel_launch entry
__device__ int  g_deg[MAX_NODES];
__device__ int2 g_bucket[MAX_NODES * BUCKET_CAP];      // (edge_id, src_node) per dst bucket

__device__ __forceinline__ float warp_sum(float v) {
    v += __shfl_xor_sync(0xffffffffu, v, 16);
    v += __shfl_xor_sync(0xffffffffu, v, 8);
    v += __shfl_xor_sync(0xffffffffu, v, 4);
    v += __shfl_xor_sync(0xffffffffu, v, 2);
    v += __shfl_xor_sync(0xffffffffu, v, 1);
    return v;
}

// ---------------------------------------------------------------------------
// Single-pass bucketing: rank via atomicAdd, direct scatter into fixed-stride
// per-node buckets.
// ---------------------------------------------------------------------------
__global__ void bucket_kernel(const int* __restrict__ edge_dst,
                              const int* __restrict__ edge_src,
                              int n_edges) {
    int i2 = (blockIdx.x * blockDim.x + threadIdx.x) * 2;
    if (i2 + 1 < n_edges) {
        const int2 d = *reinterpret_cast<const int2*>(edge_dst + i2);
        const int2 s = *reinterpret_cast<const int2*>(edge_src + i2);
        const int r0 = atomicAdd(&g_hist[d.x], 1);
        const int r1 = atomicAdd(&g_hist[d.y], 1);
        if (r0 < BUCKET_CAP) g_bucket[d.x * BUCKET_CAP + r0] = make_int2(i2 + 0, s.x);
        if (r1 < BUCKET_CAP) g_bucket[d.y * BUCKET_CAP + r1] = make_int2(i2 + 1, s.y);
    } else if (i2 < n_edges) {
        const int dd = edge_dst[i2];
        const int r = atomicAdd(&g_hist[dd], 1);
        if (r < BUCKET_CAP) g_bucket[dd * BUCKET_CAP + r] = make_int2(i2, edge_src[i2]);
    }
}

// copy hist -> deg (clamped) and restore the g_hist zero-invariant.
// Keeps all sort bookkeeping OUT of the hot fused kernel.
__global__ void deg_kernel(int n_nodes) {
    const int i4 = (blockIdx.x * blockDim.x + threadIdx.x) * 4;
    if (i4 + 3 < n_nodes) {
        int4 h = *reinterpret_cast<const int4*>(g_hist + i4);
        h.x = min(h.x, BUCKET_CAP); h.y = min(h.y, BUCKET_CAP);
        h.z = min(h.z, BUCKET_CAP); h.w = min(h.w, BUCKET_CAP);
        *reinterpret_cast<int4*>(g_deg + i4) = h;
        *reinterpret_cast<int4*>(g_hist + i4) = make_int4(0, 0, 0, 0);
    } else {
        for (int i = i4; i < n_nodes; i++) {
            g_deg[i] = min(g_hist[i], BUCKET_CAP);
            g_hist[i] = 0;
        }
    }
}

// ---------------------------------------------------------------------------
// Fused gather + depthwise TP + bias + equivariant LN.
// TWO warps per node, split by CHANNEL GROUP (fully independent — no smem,
// no barrier, no global stores besides the final output):
//   sub 0 (scalar path): xs,w0,w1  -> fields 0 (out0a), 2 (out1a)
//   sub 1 (vector path): xv,w2..w4 -> fields 1, 3, 4
// 2-edge unroll, 64-reg cap -> 4 blocks/SM. edge_weight via __ldcs, out via __stcs.
// (Body identical to the 57.8us R12 kernel; only the index source changed.)
// ---------------------------------------------------------------------------
__global__ void __launch_bounds__(256, 4) fused_tp_ln_kernel(
    const float* __restrict__ node_feat,   // (N, 320)
    const float* __restrict__ edge_sh,     // (E, 4)
    const float* __restrict__ edge_weight, // (E, 448)
    const float* __restrict__ tp_bias,     // (192,)
    const float* __restrict__ lnw,         // (448,)
    const float* __restrict__ lnb,         // (192,)
    float*       __restrict__ out,         // (N, 960)
    int n_nodes)
{
    const int warpInBlock = threadIdx.x >> 5;   // 0..7
    const int lane = threadIdx.x & 31;
    const int node = blockIdx.x * 4 + (warpInBlock >> 1);
    const int sub  = warpInBlock & 1;
    if (node >= n_nodes) return;

    const int deg = __ldg(g_deg + node);
    const float fdeg = (float)deg;
    const int2* bucket = g_bucket + (size_t)node * BUCKET_CAP;

    float* row = out + (size_t)node * 960u;

    if (sub == 0) {
        // ================= scalar path: out0a (4) + out1a (12) ================
        float a0 = 0.f, a1 = 0.f, a2 = 0.f, a3 = 0.f;
        float A[12];
#pragma unroll
        for (int i = 0; i < 12; i++) A[i] = 0.f;

        int ei = 0;
        for (; ei + 1 < deg; ei += 2) {
            const int2 es0 = __ldg(bucket + ei);
            const int2 es1 = __ldg(bucket + ei + 1);

            const float4 sh0 = __ldg(reinterpret_cast<const float4*>(edge_sh) + es0.x);
            const float4 sh1 = __ldg(reinterpret_cast<const float4*>(edge_sh) + es1.x);
            const float4 xs0 = __ldg(reinterpret_cast<const float4*>(node_feat + (size_t)es0.y * 320u) + lane);
            const float4 xs1 = __ldg(reinterpret_cast<const float4*>(node_feat + (size_t)es1.y * 320u) + lane);
            const float* wr0 = edge_weight + (size_t)es0.x * 448u;
            const float* wr1 = edge_weight + (size_t)es1.x * 448u;
            const float4 w00 = __ldcs(reinterpret_cast<const float4*>(wr0) + lane);
            const float4 w01 = __ldcs(reinterpret_cast<const float4*>(wr1) + lane);
            const float4 w10 = __ldcs(reinterpret_cast<const float4*>(wr0 + 128) + lane);
            const float4 w11 = __ldcs(reinterpret_cast<const float4*>(wr1 + 128) + lane);

            {
                const float ys = sh0.x;
                a0 += w00.x * xs0.x * ys; a1 += w00.y * xs0.y * ys;
                a2 += w00.z * xs0.z * ys; a3 += w00.w * xs0.w * ys;
                const float t0 = w10.x * xs0.x, t1 = w10.y * xs0.y;
                const float t2 = w10.z * xs0.z, t3 = w10.w * xs0.w;
                A[0] += t0 * sh0.y; A[1]  += t0 * sh0.z; A[2]  += t0 * sh0.w;
                A[3] += t1 * sh0.y; A[4]  += t1 * sh0.z; A[5]  += t1 * sh0.w;
                A[6] += t2 * sh0.y; A[7]  += t2 * sh0.z; A[8]  += t2 * sh0.w;
                A[9] += t3 * sh0.y; A[10] += t3 * sh0.z; A[11] += t3 * sh0.w;
            }
            {
                const float ys = sh1.x;
                a0 += w01.x * xs1.x * ys; a1 += w01.y * xs1.y * ys;
                a2 += w01.z * xs1.z * ys; a3 += w01.w * xs1.w * ys;
                const float t0 = w11.x * xs1.x, t1 = w11.y * xs1.y;
                const float t2 = w11.z * xs1.z, t3 = w11.w * xs1.w;
                A[0] += t0 * sh1.y; A[1]  += t0 * sh1.z; A[2]  += t0 * sh1.w;
                A[3] += t1 * sh1.y; A[4]  += t1 * sh1.z; A[5]  += t1 * sh1.w;
                A[6] += t2 * sh1.y; A[7]  += t2 * sh1.z; A[8]  += t2 * sh1.w;
                A[9] += t3 * sh1.y; A[10] += t3 * sh1.z; A[11] += t3 * sh1.w;
            }
        }
        if (ei < deg) {
            const int2 es0 = __ldg(bucket + ei);
            const float4 sh0 = __ldg(reinterpret_cast<const float4*>(edge_sh) + es0.x);
            const float4 xs0 = __ldg(reinterpret_cast<const float4*>(node_feat + (size_t)es0.y * 320u) + lane);
            const float* wr0 = edge_weight + (size_t)es0.x * 448u;
            const float4 w00 = __ldcs(reinterpret_cast<const float4*>(wr0) + lane);
            const float4 w10 = __ldcs(reinterpret_cast<const float4*>(wr0 + 128) + lane);
            const float ys = sh0.x;
            a0 += w00.x * xs0.x * ys; a1 += w00.y * xs0.y * ys;
            a2 += w00.z * xs0.z * ys; a3 += w00.w * xs0.w * ys;
            const float t0 = w10.x * xs0.x, t1 = w10.y * xs0.y;
            const float t2 = w10.z * xs0.z, t3 = w10.w * xs0.w;
            A[0] += t0 * sh0.y; A[1]  += t0 * sh0.z; A[2]  += t0 * sh0.w;
            A[3] += t1 * sh0.y; A[4]  += t1 * sh0.z; A[5]  += t1 * sh0.w;
            A[6] += t2 * sh0.y; A[7]  += t2 * sh0.z; A[8]  += t2 * sh0.w;
            A[9] += t3 * sh0.y; A[10] += t3 * sh0.z; A[11] += t3 * sh0.w;
        }

        const float4 b0 = __ldg(reinterpret_cast<const float4*>(tp_bias) + lane);
        a0 += fdeg * b0.x; a1 += fdeg * b0.y; a2 += fdeg * b0.z; a3 += fdeg * b0.w;

        float s0 = a0 + a1 + a2 + a3;
        float q0 = a0 * a0 + a1 * a1 + a2 * a2 + a3 * a3;
        float q2 = 0.f;
#pragma unroll
        for (int i = 0; i < 12; i++) q2 += A[i] * A[i];
        s0 = warp_sum(s0); q0 = warp_sum(q0); q2 = warp_sum(q2);

        const float mu0 = s0 * (1.f / 128.f);
        const float r0  = rsqrtf(fmaxf(q0 * (1.f / 128.f) - mu0 * mu0, 0.f) + LN_EPS);
        const float r2  = rsqrtf(q2 * (1.f / 384.f) + LN_EPS);

        {   // field0
            const float4 wv = __ldg(reinterpret_cast<const float4*>(lnw) + lane);
            const float4 bv = __ldg(reinterpret_cast<const float4*>(lnb) + lane);
            float4 o;
            o.x = (a0 - mu0) * r0 * wv.x + bv.x;
            o.y = (a1 - mu0) * r0 * wv.y + bv.y;
            o.z = (a2 - mu0) * r0 * wv.z + bv.z;
            o.w = (a3 - mu0) * r0 * wv.w + bv.w;
            __stcs(reinterpret_cast<float4*>(row + 4 * lane), o);
        }
        {   // field2: channels u = 4*lane + {0..3}
            const float4 wv = __ldg(reinterpret_cast<const float4*>(lnw + 192) + lane);
            const float sa = wv.x * r2, sb = wv.y * r2, sc = wv.z * r2, sd = wv.w * r2;
            __stcs(reinterpret_cast<float4*>(row + 192 + 12 * lane),
                   make_float4(A[0] * sa, A[1] * sa, A[2]  * sa, A[3]  * sb));
            __stcs(reinterpret_cast<float4*>(row + 192 + 12 * lane + 4),
                   make_float4(A[4] * sb, A[5] * sb, A[6]  * sc, A[7]  * sc));
            __stcs(reinterpret_cast<float4*>(row + 192 + 12 * lane + 8),
                   make_float4(A[8] * sc, A[9] * sd, A[10] * sd, A[11] * sd));
        }
    } else {
        // ============ vector path: out0b (2) + out1b (6) + out1c (6) ==========
        float ob0 = 0.f, ob1 = 0.f;
        float B[6], C[6];
#pragma unroll
        for (int i = 0; i < 6; i++) { B[i] = 0.f; C[i] = 0.f; }

        int ei = 0;
        for (; ei + 1 < deg; ei += 2) {
            const int2 es0 = __ldg(bucket + ei);
            const int2 es1 = __ldg(bucket + ei + 1);

            const float4 sh0 = __ldg(reinterpret_cast<const float4*>(edge_sh) + es0.x);
            const float4 sh1 = __ldg(reinterpret_cast<const float4*>(edge_sh) + es1.x);
            const float* xr0 = node_feat + (size_t)es0.y * 320u + 128u;
            const float* xr1 = node_feat + (size_t)es1.y * 320u + 128u;
            const float* wr0 = edge_weight + (size_t)es0.x * 448u;
            const float* wr1 = edge_weight + (size_t)es1.x * 448u;

            const float2 w20 = __ldcs(reinterpret_cast<const float2*>(wr0 + 256) + lane);
            const float2 w30 = __ldcs(reinterpret_cast<const float2*>(wr0 + 320) + lane);
            const float2 w40 = __ldcs(reinterpret_cast<const float2*>(wr0 + 384) + lane);
            const float2 p00 = __ldg(reinterpret_cast<const float2*>(xr0 + 6 * lane));
            const float2 p10 = __ldg(reinterpret_cast<const float2*>(xr0 + 6 * lane + 2));
            const float2 p20 = __ldg(reinterpret_cast<const float2*>(xr0 + 6 * lane + 4));

            const float2 w21 = __ldcs(reinterpret_cast<const float2*>(wr1 + 256) + lane);
            const float2 w31 = __ldcs(reinterpret_cast<const float2*>(wr1 + 320) + lane);
            const float2 w41 = __ldcs(reinterpret_cast<const float2*>(wr1 + 384) + lane);
            const float2 p01 = __ldg(reinterpret_cast<const float2*>(xr1 + 6 * lane));
            const float2 p11 = __ldg(reinterpret_cast<const float2*>(xr1 + 6 * lane + 2));
            const float2 p21 = __ldg(reinterpret_cast<const float2*>(xr1 + 6 * lane + 4));

            {
                const float ys = sh0.x, yv0 = sh0.y, yv1 = sh0.z, yv2 = sh0.w;
                const float d0 = p00.x * yv0 + p00.y * yv1 + p10.x * yv2;
                const float d1 = p10.y * yv0 + p20.x * yv1 + p20.y * yv2;
                ob0 += w30.x * d0 * INV_SQRT3;
                ob1 += w30.y * d1 * INV_SQRT3;
                const float c0 = w20.x * ys, c1 = w20.y * ys;
                B[0] += c0 * p00.x; B[1] += c0 * p00.y; B[2] += c0 * p10.x;
                B[3] += c1 * p10.y; B[4] += c1 * p20.x; B[5] += c1 * p20.y;
                const float k0 = w40.x * INV_SQRT2, k1 = w40.y * INV_SQRT2;
                C[0] += k0 * (p00.y * yv2 - p10.x * yv1);
                C[1] += k0 * (p10.x * yv0 - p00.x * yv2);
                C[2] += k0 * (p00.x * yv1 - p00.y * yv0);
                C[3] += k1 * (p20.x * yv2 - p20.y * yv1);
                C[4] += k1 * (p20.y * yv0 - p10.y * yv2);
                C[5] += k1 * (p10.y * yv1 - p20.x * yv0);
            }
            {
                const float ys = sh1.x, yv0 = sh1.y, yv1 = sh1.z, yv2 = sh1.w;
                const float d0 = p01.x * yv0 + p01.y * yv1 + p11.x * yv2;
                const float d1 = p11.y * yv0 + p21.x * yv1 + p21.y * yv2;
                ob0 += w31.x * d0 * INV_SQRT3;
                ob1 += w31.y * d1 * INV_SQRT3;
                const float c0 = w21.x * ys, c1 = w21.y * ys;
                B[0] += c0 * p01.x; B[1] += c0 * p01.y; B[2] += c0 * p11.x;
                B[3] += c1 * p11.y; B[4] += c1 * p21.x; B[5] += c1 * p21.y;
                const float k0 = w41.x * INV_SQRT2, k1 = w41.y * INV_SQRT2;
                C[0] += k0 * (p01.y * yv2 - p11.x * yv1);
                C[1] += k0 * (p11.x * yv0 - p01.x * yv2);
                C[2] += k0 * (p01.x * yv1 - p01.y * yv0);
                C[3] += k1 * (p21.x * yv2 - p21.y * yv1);
                C[4] += k1 * (p21.y * yv0 - p11.y * yv2);
                C[5] += k1 * (p11.y * yv1 - p21.x * yv0);
            }
        }
        if (ei < deg) {
            const int2 es0 = __ldg(bucket + ei);
            const float4 sh0 = __ldg(reinterpret_cast<const float4*>(edge_sh) + es0.x);
            const float* xr0 = node_feat + (size_t)es0.y * 320u + 128u;
            const float* wr0 = edge_weight + (size_t)es0.x * 448u;
            const float2 w20 = __ldcs(reinterpret_cast<const float2*>(wr0 + 256) + lane);
            const float2 w30 = __ldcs(reinterpret_cast<const float2*>(wr0 + 320) + lane);
            const float2 w40 = __ldcs(reinterpret_cast<const float2*>(wr0 + 384) + lane);
            const float2 p00 = __ldg(reinterpret_cast<const float2*>(xr0 + 6 * lane));
            const float2 p10 = __ldg(reinterpret_cast<const float2*>(xr0 + 6 * lane + 2));
            const float2 p20 = __ldg(reinterpret_cast<const float2*>(xr0 + 6 * lane + 4));
            const float ys = sh0.x, yv0 = sh0.y, yv1 = sh0.z, yv2 = sh0.w;
            const float d0 = p00.x * yv0 + p00.y * yv1 + p10.x * yv2;
            const float d1 = p10.y * yv0 + p20.x * yv1 + p20.y * yv2;
            ob0 += w30.x * d0 * INV_SQRT3;
            ob1 += w30.y * d1 * INV_SQRT3;
            const float c0 = w20.x * ys, c1 = w20.y * ys;
            B[0] += c0 * p00.x; B[1] += c0 * p00.y; B[2] += c0 * p10.x;
            B[3] += c1 * p10.y; B[4] += c1 * p20.x; B[5] += c1 * p20.y;
            const float k0 = w40.x * INV_SQRT2, k1 = w40.y * INV_SQRT2;
            C[0] += k0 * (p00.y * yv2 - p10.x * yv1);
            C[1] += k0 * (p10.x * yv0 - p00.x * yv2);
            C[2] += k0 * (p00.x * yv1 - p00.y * yv0);
            C[3] += k1 * (p20.x * yv2 - p20.y * yv1);
            C[4] += k1 * (p20.y * yv0 - p10.y * yv2);
            C[5] += k1 * (p10.y * yv1 - p20.x * yv0);
        }

        const float2 bb = __ldg(reinterpret_cast<const float2*>(tp_bias + 128) + lane);
        ob0 += fdeg * bb.x; ob1 += fdeg * bb.y;

        float s1 = ob0 + ob1;
        float q1 = ob0 * ob0 + ob1 * ob1;
        float q3 = 0.f, q4 = 0.f;
#pragma unroll
        for (int i = 0; i < 6; i++) { q3 += B[i] * B[i]; q4 += C[i] * C[i]; }
        s1 = warp_sum(s1); q1 = warp_sum(q1);
        q3 = warp_sum(q3); q4 = warp_sum(q4);

        const float mu1 = s1 * (1.f / 64.f);
        const float r1  = rsqrtf(fmaxf(q1 * (1.f / 64.f) - mu1 * mu1, 0.f) + LN_EPS);
        const float r3  = rsqrtf(q3 * (1.f / 192.f) + LN_EPS);
        const float r4  = rsqrtf(q4 * (1.f / 192.f) + LN_EPS);

        {   // field1
            const float2 wv = __ldg(reinterpret_cast<const float2*>(lnw + 128) + lane);
            const float2 bv = __ldg(reinterpret_cast<const float2*>(lnb + 128) + lane);
            float2 o;
            o.x = (ob0 - mu1) * r1 * wv.x + bv.x;
            o.y = (ob1 - mu1) * r1 * wv.y + bv.y;
            __stcs(reinterpret_cast<float2*>(row + 128 + 2 * lane), o);
        }
        {   // field3
            const float2 wv = __ldg(reinterpret_cast<const float2*>(lnw + 320) + lane);
            const float sa = wv.x * r3, sb = wv.y * r3;
            __stcs(reinterpret_cast<float2*>(row + 576 + 6 * lane),     make_float2(B[0] * sa, B[1] * sa));
            __stcs(reinterpret_cast<float2*>(row + 576 + 6 * lane + 2), make_float2(B[2] * sa, B[3] * sb));
            __stcs(reinterpret_cast<float2*>(row + 576 + 6 * lane + 4), make_float2(B[4] * sb, B[5] * sb));
        }
        {   // field4
            const float2 wv = __ldg(reinterpret_cast<const float2*>(lnw + 384) + lane);
            const float sa = wv.x * r4, sb = wv.y * r4;
            __stcs(reinterpret_cast<float2*>(row + 768 + 6 * lane),     make_float2(C[0] * sa, C[1] * sa));
            __stcs(reinterpret_cast<float2*>(row + 768 + 6 * lane + 2), make_float2(C[2] * sa, C[3] * sb));
            __stcs(reinterpret_cast<float2*>(row + 768 + 6 * lane + 4), make_float2(C[4] * sb, C[5] * sb));
        }
    }
}

// ---------------------------------------------------------------------------
extern "C" void kernel_launch(void* const* d_in, const int* in_sizes, int n_in,
                              void* d_out, int out_size)
{
    const float* node_feat   = (const float*)d_in[0];
    const float* edge_sh     = (const float*)d_in[1];
    const float* edge_weight = (const float*)d_in[2];
    const float* tp_bias     = (const float*)d_in[3];
    const float* ln_weight   = (const float*)d_in[4];
    const float* ln_bias     = (const float*)d_in[5];
    const int*   edge_src    = (const int*)d_in[6];
    const int*   edge_dst    = (const int*)d_in[7];
    float* out = (float*)d_out;

    const int n_nodes = in_sizes[0] / 320;
    const int n_edges = in_sizes[7];

    // single-pass bucketing
    {
        const int threads = (n_edges + 1) / 2;
        bucket_kernel<<<(threads + 255) / 256, 256>>>(edge_dst, edge_src, n_edges);
    }
    // deg snapshot + hist re-zero (restores entry invariant)
    {
        const int threads = (n_nodes + 3) / 4;
        deg_kernel<<<(threads + 255) / 256, 256>>>(n_nodes);
    }

    // 2 warps per node (channel-split), 4 nodes per 256-thread block
    const int blocks = (n_nodes + 3) / 4;
    fused_tp_ln_kernel<<<blocks, 256>>>(node_feat, edge_sh, edge_weight,
                                        tp_bias, ln_weight, ln_bias,
                                        out, n_nodes);
}

// round 15
// speedup vs baseline: 1.4182x; 1.0035x over previous
#include <cuda_runtime.h>
#include <cuda_bf16.h>
#include <cstdint>

#define INV_SQRT3 0.57735026918962576451f
#define INV_SQRT2 0.70710678118654752440f
#define LN_EPS 1e-5f

#define MAX_NODES 16384
#define MAX_EDGES 131072
#define BUCKET_CAP 64   // max degree ~27 for Poisson(8); 64 is >>10 sigma

// scratch (allocation-free rule: __device__ globals; statically zero-initialized)
__device__ int  g_hist[MAX_NODES];                     // ALWAYS zero at kernel_launch entry
__device__ int  g_deg[MAX_NODES];
__device__ int2 g_bucket[MAX_NODES * BUCKET_CAP];      // (edge_id, src_node) per dst bucket

__device__ __forceinline__ float warp_sum(float v) {
    v += __shfl_xor_sync(0xffffffffu, v, 16);
    v += __shfl_xor_sync(0xffffffffu, v, 8);
    v += __shfl_xor_sync(0xffffffffu, v, 4);
    v += __shfl_xor_sync(0xffffffffu, v, 2);
    v += __shfl_xor_sync(0xffffffffu, v, 1);
    return v;
}

// ---------------------------------------------------------------------------
// Single-pass bucketing: 1 edge per thread (maximum chip-wide concurrency for
// the load -> atomicAdd -> dependent-store chain).
// ---------------------------------------------------------------------------
__global__ void bucket_kernel(const int* __restrict__ edge_dst,
                              const int* __restrict__ edge_src,
                              int n_edges) {
    const int i = blockIdx.x * blockDim.x + threadIdx.x;
    if (i < n_edges) {
        const int dd = __ldg(edge_dst + i);
        const int ss = __ldg(edge_src + i);
        const int r = atomicAdd(&g_hist[dd], 1);
        if (r < BUCKET_CAP) g_bucket[dd * BUCKET_CAP + r] = make_int2(i, ss);
    }
}

// copy hist -> deg (clamped) and restore the g_hist zero-invariant.
// Keeps all sort bookkeeping OUT of the hot fused kernel.
__global__ void deg_kernel(int n_nodes) {
    const int i4 = (blockIdx.x * blockDim.x + threadIdx.x) * 4;
    if (i4 + 3 < n_nodes) {
        int4 h = *reinterpret_cast<const int4*>(g_hist + i4);
        h.x = min(h.x, BUCKET_CAP); h.y = min(h.y, BUCKET_CAP);
        h.z = min(h.z, BUCKET_CAP); h.w = min(h.w, BUCKET_CAP);
        *reinterpret_cast<int4*>(g_deg + i4) = h;
        *reinterpret_cast<int4*>(g_hist + i4) = make_int4(0, 0, 0, 0);
    } else {
        for (int i = i4; i < n_nodes; i++) {
            g_deg[i] = min(g_hist[i], BUCKET_CAP);
            g_hist[i] = 0;
        }
    }
}

// ---------------------------------------------------------------------------
// Fused gather + depthwise TP + bias + equivariant LN.
// TWO warps per node, split by CHANNEL GROUP (fully independent — no smem,
// no barrier, no global stores besides the final output):
//   sub 0 (scalar path): xs,w0,w1  -> fields 0 (out0a), 2 (out1a)
//   sub 1 (vector path): xv,w2..w4 -> fields 1, 3, 4
// 2-edge unroll, 64-reg cap -> 4 blocks/SM. edge_weight via __ldcs, out via __stcs.
// ---------------------------------------------------------------------------
__global__ void __launch_bounds__(256, 4) fused_tp_ln_kernel(
    const float* __restrict__ node_feat,   // (N, 320)
    const float* __restrict__ edge_sh,     // (E, 4)
    const float* __restrict__ edge_weight, // (E, 448)
    const float* __restrict__ tp_bias,     // (192,)
    const float* __restrict__ lnw,         // (448,)
    const float* __restrict__ lnb,         // (192,)
    float*       __restrict__ out,         // (N, 960)
    int n_nodes)
{
    const int warpInBlock = threadIdx.x >> 5;   // 0..7
    const int lane = threadIdx.x & 31;
    const int node = blockIdx.x * 4 + (warpInBlock >> 1);
    const int sub  = warpInBlock & 1;
    if (node >= n_nodes) return;

    const int deg = __ldg(g_deg + node);
    const float fdeg = (float)deg;
    const int2* bucket = g_bucket + (size_t)node * BUCKET_CAP;

    float* row = out + (size_t)node * 960u;

    if (sub == 0) {
        // ================= scalar path: out0a (4) + out1a (12) ================
        float a0 = 0.f, a1 = 0.f, a2 = 0.f, a3 = 0.f;
        float A[12];
#pragma unroll
        for (int i = 0; i < 12; i++) A[i] = 0.f;

        int ei = 0;
        for (; ei + 1 < deg; ei += 2) {
            const int2 es0 = __ldg(bucket + ei);
            const int2 es1 = __ldg(bucket + ei + 1);

            const float4 sh0 = __ldg(reinterpret_cast<const float4*>(edge_sh) + es0.x);
            const float4 sh1 = __ldg(reinterpret_cast<const float4*>(edge_sh) + es1.x);
            const float4 xs0 = __ldg(reinterpret_cast<const float4*>(node_feat + (size_t)es0.y * 320u) + lane);
            const float4 xs1 = __ldg(reinterpret_cast<const float4*>(node_feat + (size_t)es1.y * 320u) + lane);
            const float* wr0 = edge_weight + (size_t)es0.x * 448u;
            const float* wr1 = edge_weight + (size_t)es1.x * 448u;
            const float4 w00 = __ldcs(reinterpret_cast<const float4*>(wr0) + lane);
            const float4 w01 = __ldcs(reinterpret_cast<const float4*>(wr1) + lane);
            const float4 w10 = __ldcs(reinterpret_cast<const float4*>(wr0 + 128) + lane);
            const float4 w11 = __ldcs(reinterpret_cast<const float4*>(wr1 + 128) + lane);

            {
                const float ys = sh0.x;
                a0 += w00.x * xs0.x * ys; a1 += w00.y * xs0.y * ys;
                a2 += w00.z * xs0.z * ys; a3 += w00.w * xs0.w * ys;
                const float t0 = w10.x * xs0.x, t1 = w10.y * xs0.y;
                const float t2 = w10.z * xs0.z, t3 = w10.w * xs0.w;
                A[0] += t0 * sh0.y; A[1]  += t0 * sh0.z; A[2]  += t0 * sh0.w;
                A[3] += t1 * sh0.y; A[4]  += t1 * sh0.z; A[5]  += t1 * sh0.w;
                A[6] += t2 * sh0.y; A[7]  += t2 * sh0.z; A[8]  += t2 * sh0.w;
                A[9] += t3 * sh0.y; A[10] += t3 * sh0.z; A[11] += t3 * sh0.w;
            }
            {
                const float ys = sh1.x;
                a0 += w01.x * xs1.x * ys; a1 += w01.y * xs1.y * ys;
                a2 += w01.z * xs1.z * ys; a3 += w01.w * xs1.w * ys;
                const float t0 = w11.x * xs1.x, t1 = w11.y * xs1.y;
                const float t2 = w11.z * xs1.z, t3 = w11.w * xs1.w;
                A[0] += t0 * sh1.y; A[1]  += t0 * sh1.z; A[2]  += t0 * sh1.w;
                A[3] += t1 * sh1.y; A[4]  += t1 * sh1.z; A[5]  += t1 * sh1.w;
                A[6] += t2 * sh1.y; A[7]  += t2 * sh1.z; A[8]  += t2 * sh1.w;
                A[9] += t3 * sh1.y; A[10] += t3 * sh1.z; A[11] += t3 * sh1.w;
            }
        }
        if (ei < deg) {
            const int2 es0 = __ldg(bucket + ei);
            const float4 sh0 = __ldg(reinterpret_cast<const float4*>(edge_sh) + es0.x);
            const float4 xs0 = __ldg(reinterpret_cast<const float4*>(node_feat + (size_t)es0.y * 320u) + lane);
            const float* wr0 = edge_weight + (size_t)es0.x * 448u;
            const float4 w00 = __ldcs(reinterpret_cast<const float4*>(wr0) + lane);
            const float4 w10 = __ldcs(reinterpret_cast<const float4*>(wr0 + 128) + lane);
            const float ys = sh0.x;
            a0 += w00.x * xs0.x * ys; a1 += w00.y * xs0.y * ys;
            a2 += w00.z * xs0.z * ys; a3 += w00.w * xs0.w * ys;
            const float t0 = w10.x * xs0.x, t1 = w10.y * xs0.y;
            const float t2 = w10.z * xs0.z, t3 = w10.w * xs0.w;
            A[0] += t0 * sh0.y; A[1]  += t0 * sh0.z; A[2]  += t0 * sh0.w;
            A[3] += t1 * sh0.y; A[4]  += t1 * sh0.z; A[5]  += t1 * sh0.w;
            A[6] += t2 * sh0.y; A[7]  += t2 * sh0.z; A[8]  += t2 * sh0.w;
            A[9] += t3 * sh0.y; A[10] += t3 * sh0.z; A[11] += t3 * sh0.w;
        }

        const float4 b0 = __ldg(reinterpret_cast<const float4*>(tp_bias) + lane);
        a0 += fdeg * b0.x; a1 += fdeg * b0.y; a2 += fdeg * b0.z; a3 += fdeg * b0.w;

        float s0 = a0 + a1 + a2 + a3;
        float q0 = a0 * a0 + a1 * a1 + a2 * a2 + a3 * a3;
        float q2 = 0.f;
#pragma unroll
        for (int i = 0; i < 12; i++) q2 += A[i] * A[i];
        s0 = warp_sum(s0); q0 = warp_sum(q0); q2 = warp_sum(q2);

        const float mu0 = s0 * (1.f / 128.f);
        const float r0  = rsqrtf(fmaxf(q0 * (1.f / 128.f) - mu0 * mu0, 0.f) + LN_EPS);
        const float r2  = rsqrtf(q2 * (1.f / 384.f) + LN_EPS);

        {   // field0
            const float4 wv = __ldg(reinterpret_cast<const float4*>(lnw) + lane);
            const float4 bv = __ldg(reinterpret_cast<const float4*>(lnb) + lane);
            float4 o;
            o.x = (a0 - mu0) * r0 * wv.x + bv.x;
            o.y = (a1 - mu0) * r0 * wv.y + bv.y;
            o.z = (a2 - mu0) * r0 * wv.z + bv.z;
            o.w = (a3 - mu0) * r0 * wv.w + bv.w;
            __stcs(reinterpret_cast<float4*>(row + 4 * lane), o);
        }
        {   // field2: channels u = 4*lane + {0..3}
            const float4 wv = __ldg(reinterpret_cast<const float4*>(lnw + 192) + lane);
            const float sa = wv.x * r2, sb = wv.y * r2, sc = wv.z * r2, sd = wv.w * r2;
            __stcs(reinterpret_cast<float4*>(row + 192 + 12 * lane),
                   make_float4(A[0] * sa, A[1] * sa, A[2]  * sa, A[3]  * sb));
            __stcs(reinterpret_cast<float4*>(row + 192 + 12 * lane + 4),
                   make_float4(A[4] * sb, A[5] * sb, A[6]  * sc, A[7]  * sc));
            __stcs(reinterpret_cast<float4*>(row + 192 + 12 * lane + 8),
                   make_float4(A[8] * sc, A[9] * sd, A[10] * sd, A[11] * sd));
        }
    } else {
        // ============ vector path: out0b (2) + out1b (6) + out1c (6) ==========
        float ob0 = 0.f, ob1 = 0.f;
        float B[6], C[6];
#pragma unroll
        for (int i = 0; i < 6; i++) { B[i] = 0.f; C[i] = 0.f; }

        int ei = 0;
        for (; ei + 1 < deg; ei += 2) {
            const int2 es0 = __ldg(bucket + ei);
            const int2 es1 = __ldg(bucket + ei + 1);

            const float4 sh0 = __ldg(reinterpret_cast<const float4*>(edge_sh) + es0.x);
            const float4 sh1 = __ldg(reinterpret_cast<const float4*>(edge_sh) + es1.x);
            const float* xr0 = node_feat + (size_t)es0.y * 320u + 128u;
            const float* xr1 = node_feat + (size_t)es1.y * 320u + 128u;
            const float* wr0 = edge_weight + (size_t)es0.x * 448u;
            const float* wr1 = edge_weight + (size_t)es1.x * 448u;

            const float2 w20 = __ldcs(reinterpret_cast<const float2*>(wr0 + 256) + lane);
            const float2 w30 = __ldcs(reinterpret_cast<const float2*>(wr0 + 320) + lane);
            const float2 w40 = __ldcs(reinterpret_cast<const float2*>(wr0 + 384) + lane);
            const float2 p00 = __ldg(reinterpret_cast<const float2*>(xr0 + 6 * lane));
            const float2 p10 = __ldg(reinterpret_cast<const float2*>(xr0 + 6 * lane + 2));
            const float2 p20 = __ldg(reinterpret_cast<const float2*>(xr0 + 6 * lane + 4));

            const float2 w21 = __ldcs(reinterpret_cast<const float2*>(wr1 + 256) + lane);
            const float2 w31 = __ldcs(reinterpret_cast<const float2*>(wr1 + 320) + lane);
            const float2 w41 = __ldcs(reinterpret_cast<const float2*>(wr1 + 384) + lane);
            const float2 p01 = __ldg(reinterpret_cast<const float2*>(xr1 + 6 * lane));
            const float2 p11 = __ldg(reinterpret_cast<const float2*>(xr1 + 6 * lane + 2));
            const float2 p21 = __ldg(reinterpret_cast<const float2*>(xr1 + 6 * lane + 4));

            {
                const float ys = sh0.x, yv0 = sh0.y, yv1 = sh0.z, yv2 = sh0.w;
                const float d0 = p00.x * yv0 + p00.y * yv1 + p10.x * yv2;
                const float d1 = p10.y * yv0 + p20.x * yv1 + p20.y * yv2;
                ob0 += w30.x * d0 * INV_SQRT3;
                ob1 += w30.y * d1 * INV_SQRT3;
                const float c0 = w20.x * ys, c1 = w20.y * ys;
                B[0] += c0 * p00.x; B[1] += c0 * p00.y; B[2] += c0 * p10.x;
                B[3] += c1 * p10.y; B[4] += c1 * p20.x; B[5] += c1 * p20.y;
                const float k0 = w40.x * INV_SQRT2, k1 = w40.y * INV_SQRT2;
                C[0] += k0 * (p00.y * yv2 - p10.x * yv1);
                C[1] += k0 * (p10.x * yv0 - p00.x * yv2);
                C[2] += k0 * (p00.x * yv1 - p00.y * yv0);
                C[3] += k1 * (p20.x * yv2 - p20.y * yv1);
                C[4] += k1 * (p20.y * yv0 - p10.y * yv2);
                C[5] += k1 * (p10.y * yv1 - p20.x * yv0);
            }
            {
                const float ys = sh1.x, yv0 = sh1.y, yv1 = sh1.z, yv2 = sh1.w;
                const float d0 = p01.x * yv0 + p01.y * yv1 + p11.x * yv2;
                const float d1 = p11.y * yv0 + p21.x * yv1 + p21.y * yv2;
                ob0 += w31.x * d0 * INV_SQRT3;
                ob1 += w31.y * d1 * INV_SQRT3;
                const float c0 = w21.x * ys, c1 = w21.y * ys;
                B[0] += c0 * p01.x; B[1] += c0 * p01.y; B[2] += c0 * p11.x;
                B[3] += c1 * p11.y; B[4] += c1 * p21.x; B[5] += c1 * p21.y;
                const float k0 = w41.x * INV_SQRT2, k1 = w41.y * INV_SQRT2;
                C[0] += k0 * (p01.y * yv2 - p11.x * yv1);
                C[1] += k0 * (p11.x * yv0 - p01.x * yv2);
                C[2] += k0 * (p01.x * yv1 - p01.y * yv0);
                C[3] += k1 * (p21.x * yv2 - p21.y * yv1);
                C[4] += k1 * (p21.y * yv0 - p11.y * yv2);
                C[5] += k1 * (p11.y * yv1 - p21.x * yv0);
            }
        }
        if (ei < deg) {
            const int2 es0 = __ldg(bucket + ei);
            const float4 sh0 = __ldg(reinterpret_cast<const float4*>(edge_sh) + es0.x);
            const float* xr0 = node_feat + (size_t)es0.y * 320u + 128u;
            const float* wr0 = edge_weight + (size_t)es0.x * 448u;
            const float2 w20 = __ldcs(reinterpret_cast<const float2*>(wr0 + 256) + lane);
            const float2 w30 = __ldcs(reinterpret_cast<const float2*>(wr0 + 320) + lane);
            const float2 w40 = __ldcs(reinterpret_cast<const float2*>(wr0 + 384) + lane);
            const float2 p00 = __ldg(reinterpret_cast<const float2*>(xr0 + 6 * lane));
            const float2 p10 = __ldg(reinterpret_cast<const float2*>(xr0 + 6 * lane + 2));
            const float2 p20 = __ldg(reinterpret_cast<const float2*>(xr0 + 6 * lane + 4));
            const float ys = sh0.x, yv0 = sh0.y, yv1 = sh0.z, yv2 = sh0.w;
            const float d0 = p00.x * yv0 + p00.y * yv1 + p10.x * yv2;
            const float d1 = p10.y * yv0 + p20.x * yv1 + p20.y * yv2;
            ob0 += w30.x * d0 * INV_SQRT3;
            ob1 += w30.y * d1 * INV_SQRT3;
            const float c0 = w20.x * ys, c1 = w20.y * ys;
            B[0] += c0 * p00.x; B[1] += c0 * p00.y; B[2] += c0 * p10.x;
            B[3] += c1 * p10.y; B[4] += c1 * p20.x; B[5] += c1 * p20.y;
            const float k0 = w40.x * INV_SQRT2, k1 = w40.y * INV_SQRT2;
            C[0] += k0 * (p00.y * yv2 - p10.x * yv1);
            C[1] += k0 * (p10.x * yv0 - p00.x * yv2);
            C[2] += k0 * (p00.x * yv1 - p00.y * yv0);
            C[3] += k1 * (p20.x * yv2 - p20.y * yv1);
            C[4] += k1 * (p20.y * yv0 - p10.y * yv2);
            C[5] += k1 * (p10.y * yv1 - p20.x * yv0);
        }

        const float2 bb = __ldg(reinterpret_cast<const float2*>(tp_bias + 128) + lane);
        ob0 += fdeg * bb.x; ob1 += fdeg * bb.y;

        float s1 = ob0 + ob1;
        float q1 = ob0 * ob0 + ob1 * ob1;
        float q3 = 0.f, q4 = 0.f;
#pragma unroll
        for (int i = 0; i < 6; i++) { q3 += B[i] * B[i]; q4 += C[i] * C[i]; }
        s1 = warp_sum(s1); q1 = warp_sum(q1);
        q3 = warp_sum(q3); q4 = warp_sum(q4);

        const float mu1 = s1 * (1.f / 64.f);
        const float r1  = rsqrtf(fmaxf(q1 * (1.f / 64.f) - mu1 * mu1, 0.f) + LN_EPS);
        const float r3  = rsqrtf(q3 * (1.f / 192.f) + LN_EPS);
        const float r4  = rsqrtf(q4 * (1.f / 192.f) + LN_EPS);

        {   // field1
            const float2 wv = __ldg(reinterpret_cast<const float2*>(lnw + 128) + lane);
            const float2 bv = __ldg(reinterpret_cast<const float2*>(lnb + 128) + lane);
            float2 o;
            o.x = (ob0 - mu1) * r1 * wv.x + bv.x;
            o.y = (ob1 - mu1) * r1 * wv.y + bv.y;
            __stcs(reinterpret_cast<float2*>(row + 128 + 2 * lane), o);
        }
        {   // field3
            const float2 wv = __ldg(reinterpret_cast<const float2*>(lnw + 320) + lane);
            const float sa = wv.x * r3, sb = wv.y * r3;
            __stcs(reinterpret_cast<float2*>(row + 576 + 6 * lane),     make_float2(B[0] * sa, B[1] * sa));
            __stcs(reinterpret_cast<float2*>(row + 576 + 6 * lane + 2), make_float2(B[2] * sa, B[3] * sb));
            __stcs(reinterpret_cast<float2*>(row + 576 + 6 * lane + 4), make_float2(B[4] * sb, B[5] * sb));
        }
        {   // field4
            const float2 wv = __ldg(reinterpret_cast<const float2*>(lnw + 384) + lane);
            const float sa = wv.x * r4, sb = wv.y * r4;
            __stcs(reinterpret_cast<float2*>(row + 768 + 6 * lane),     make_float2(C[0] * sa, C[1] * sa));
            __stcs(reinterpret_cast<float2*>(row + 768 + 6 * lane + 2), make_float2(C[2] * sa, C[3] * sb));
            __stcs(reinterpret_cast<float2*>(row + 768 + 6 * lane + 4), make_float2(C[4] * sb, C[5] * sb));
        }
    }
}

// ---------------------------------------------------------------------------
extern "C" void kernel_launch(void* const* d_in, const int* in_sizes, int n_in,
                              void* d_out, int out_size)
{
    const float* node_feat   = (const float*)d_in[0];
    const float* edge_sh     = (const float*)d_in[1];
    const float* edge_weight = (const float*)d_in[2];
    const float* tp_bias     = (const float*)d_in[3];
    const float* ln_weight   = (const float*)d_in[4];
    const float* ln_bias     = (const float*)d_in[5];
    const int*   edge_src    = (const int*)d_in[6];
    const int*   edge_dst    = (const int*)d_in[7];
    float* out = (float*)d_out;

    const int n_nodes = in_sizes[0] / 320;
    const int n_edges = in_sizes[7];

    // single-pass bucketing, 1 edge per thread
    bucket_kernel<<<(n_edges + 255) / 256, 256>>>(edge_dst, edge_src, n_edges);

    // deg snapshot + hist re-zero (restores entry invariant)
    {
        const int threads = (n_nodes + 3) / 4;
        deg_kernel<<<(threads + 255) / 256, 256>>>(n_nodes);
    }

    // 2 warps per node (channel-split), 4 nodes per 256-thread block
    const int blocks = (n_nodes + 3) / 4;
    fused_tp_ln_kernel<<<blocks, 256>>>(node_feat, edge_sh, edge_weight,
                                        tp_bias, ln_weight, ln_bias,
                                        out, n_nodes);
}

// round 16
// speedup vs baseline: 1.4651x; 1.0331x over previous
#include <cuda_runtime.h>
#include <cuda_bf16.h>
#include <cstdint>

#define INV_SQRT3 0.57735026918962576451f
#define INV_SQRT2 0.70710678118654752440f
#define LN_EPS 1e-5f

#define MAX_NODES 16384
#define MAX_EDGES 131072
#define BUCKET_CAP 64   // max degree ~27 for Poisson(8); 64 is >>10 sigma

// scratch (allocation-free rule: __device__ globals; statically zero-initialized)
__device__ int  g_hist[MAX_NODES];                     // ALWAYS zero at kernel_launch entry
__device__ int  g_deg[MAX_NODES];
__device__ int2 g_bucket[MAX_NODES * BUCKET_CAP];      // (edge_id, src_node) per dst bucket

__device__ __forceinline__ float warp_sum(float v) {
    v += __shfl_xor_sync(0xffffffffu, v, 16);
    v += __shfl_xor_sync(0xffffffffu, v, 8);
    v += __shfl_xor_sync(0xffffffffu, v, 4);
    v += __shfl_xor_sync(0xffffffffu, v, 2);
    v += __shfl_xor_sync(0xffffffffu, v, 1);
    return v;
}

// ---------------------------------------------------------------------------
// Single-pass bucketing: 1 edge per thread.
// ---------------------------------------------------------------------------
__global__ void bucket_kernel(const int* __restrict__ edge_dst,
                              const int* __restrict__ edge_src,
                              int n_edges) {
    const int i = blockIdx.x * blockDim.x + threadIdx.x;
    if (i < n_edges) {
        const int dd = __ldg(edge_dst + i);
        const int ss = __ldg(edge_src + i);
        const int r = atomicAdd(&g_hist[dd], 1);
        if (r < BUCKET_CAP) g_bucket[dd * BUCKET_CAP + r] = make_int2(i, ss);
    }
}

// copy hist -> deg (clamped) and restore the g_hist zero-invariant.
__global__ void deg_kernel(int n_nodes) {
    const int i4 = (blockIdx.x * blockDim.x + threadIdx.x) * 4;
    if (i4 + 3 < n_nodes) {
        int4 h = *reinterpret_cast<const int4*>(g_hist + i4);
        h.x = min(h.x, BUCKET_CAP); h.y = min(h.y, BUCKET_CAP);
        h.z = min(h.z, BUCKET_CAP); h.w = min(h.w, BUCKET_CAP);
        *reinterpret_cast<int4*>(g_deg + i4) = h;
        *reinterpret_cast<int4*>(g_hist + i4) = make_int4(0, 0, 0, 0);
    } else {
        for (int i = i4; i < n_nodes; i++) {
            g_deg[i] = min(g_hist[i], BUCKET_CAP);
            g_hist[i] = 0;
        }
    }
}

// ---------------------------------------------------------------------------
// Fused gather + depthwise TP + bias + equivariant LN.
// TWO warps per node, split by CHANNEL GROUP (fully independent):
//   sub 0 (scalar path): xs,w0,w1  -> fields 0 (out0a), 2 (out1a)
//   sub 1 (vector path): xv,w2..w4 -> fields 1, 3, 4
// 128-thread blocks (2 nodes each) for finer work-stealing granularity /
// smaller straggler tail; 8 blocks/SM keeps 32 warps/SM at <=64 regs.
// edge_weight via __ldcs, outputs via __stcs.
// ---------------------------------------------------------------------------
__global__ void __launch_bounds__(128, 8) fused_tp_ln_kernel(
    const float* __restrict__ node_feat,   // (N, 320)
    const float* __restrict__ edge_sh,     // (E, 4)
    const float* __restrict__ edge_weight, // (E, 448)
    const float* __restrict__ tp_bias,     // (192,)
    const float* __restrict__ lnw,         // (448,)
    const float* __restrict__ lnb,         // (192,)
    float*       __restrict__ out,         // (N, 960)
    int n_nodes)
{
    const int warpInBlock = threadIdx.x >> 5;   // 0..3
    const int lane = threadIdx.x & 31;
    const int node = blockIdx.x * 2 + (warpInBlock >> 1);
    const int sub  = warpInBlock & 1;
    if (node >= n_nodes) return;

    const int deg = __ldg(g_deg + node);
    const float fdeg = (float)deg;
    const int2* bucket = g_bucket + (size_t)node * BUCKET_CAP;

    float* row = out + (size_t)node * 960u;

    if (sub == 0) {
        // ================= scalar path: out0a (4) + out1a (12) ================
        float a0 = 0.f, a1 = 0.f, a2 = 0.f, a3 = 0.f;
        float A[12];
#pragma unroll
        for (int i = 0; i < 12; i++) A[i] = 0.f;

        int ei = 0;
        for (; ei + 1 < deg; ei += 2) {
            const int2 es0 = __ldg(bucket + ei);
            const int2 es1 = __ldg(bucket + ei + 1);

            const float4 sh0 = __ldg(reinterpret_cast<const float4*>(edge_sh) + es0.x);
            const float4 sh1 = __ldg(reinterpret_cast<const float4*>(edge_sh) + es1.x);
            const float4 xs0 = __ldg(reinterpret_cast<const float4*>(node_feat + (size_t)es0.y * 320u) + lane);
            const float4 xs1 = __ldg(reinterpret_cast<const float4*>(node_feat + (size_t)es1.y * 320u) + lane);
            const float* wr0 = edge_weight + (size_t)es0.x * 448u;
            const float* wr1 = edge_weight + (size_t)es1.x * 448u;
            const float4 w00 = __ldcs(reinterpret_cast<const float4*>(wr0) + lane);
            const float4 w01 = __ldcs(reinterpret_cast<const float4*>(wr1) + lane);
            const float4 w10 = __ldcs(reinterpret_cast<const float4*>(wr0 + 128) + lane);
            const float4 w11 = __ldcs(reinterpret_cast<const float4*>(wr1 + 128) + lane);

            {
                const float ys = sh0.x;
                a0 += w00.x * xs0.x * ys; a1 += w00.y * xs0.y * ys;
                a2 += w00.z * xs0.z * ys; a3 += w00.w * xs0.w * ys;
                const float t0 = w10.x * xs0.x, t1 = w10.y * xs0.y;
                const float t2 = w10.z * xs0.z, t3 = w10.w * xs0.w;
                A[0] += t0 * sh0.y; A[1]  += t0 * sh0.z; A[2]  += t0 * sh0.w;
                A[3] += t1 * sh0.y; A[4]  += t1 * sh0.z; A[5]  += t1 * sh0.w;
                A[6] += t2 * sh0.y; A[7]  += t2 * sh0.z; A[8]  += t2 * sh0.w;
                A[9] += t3 * sh0.y; A[10] += t3 * sh0.z; A[11] += t3 * sh0.w;
            }
            {
                const float ys = sh1.x;
                a0 += w01.x * xs1.x * ys; a1 += w01.y * xs1.y * ys;
                a2 += w01.z * xs1.z * ys; a3 += w01.w * xs1.w * ys;
                const float t0 = w11.x * xs1.x, t1 = w11.y * xs1.y;
                const float t2 = w11.z * xs1.z, t3 = w11.w * xs1.w;
                A[0] += t0 * sh1.y; A[1]  += t0 * sh1.z; A[2]  += t0 * sh1.w;
                A[3] += t1 * sh1.y; A[4]  += t1 * sh1.z; A[5]  += t1 * sh1.w;
                A[6] += t2 * sh1.y; A[7]  += t2 * sh1.z; A[8]  += t2 * sh1.w;
                A[9] += t3 * sh1.y; A[10] += t3 * sh1.z; A[11] += t3 * sh1.w;
            }
        }
        if (ei < deg) {
            const int2 es0 = __ldg(bucket + ei);
            const float4 sh0 = __ldg(reinterpret_cast<const float4*>(edge_sh) + es0.x);
            const float4 xs0 = __ldg(reinterpret_cast<const float4*>(node_feat + (size_t)es0.y * 320u) + lane);
            const float* wr0 = edge_weight + (size_t)es0.x * 448u;
            const float4 w00 = __ldcs(reinterpret_cast<const float4*>(wr0) + lane);
            const float4 w10 = __ldcs(reinterpret_cast<const float4*>(wr0 + 128) + lane);
            const float ys = sh0.x;
            a0 += w00.x * xs0.x * ys; a1 += w00.y * xs0.y * ys;
            a2 += w00.z * xs0.z * ys; a3 += w00.w * xs0.w * ys;
            const float t0 = w10.x * xs0.x, t1 = w10.y * xs0.y;
            const float t2 = w10.z * xs0.z, t3 = w10.w * xs0.w;
            A[0] += t0 * sh0.y; A[1]  += t0 * sh0.z; A[2]  += t0 * sh0.w;
            A[3] += t1 * sh0.y; A[4]  += t1 * sh0.z; A[5]  += t1 * sh0.w;
            A[6] += t2 * sh0.y; A[7]  += t2 * sh0.z; A[8]  += t2 * sh0.w;
            A[9] += t3 * sh0.y; A[10] += t3 * sh0.z; A[11] += t3 * sh0.w;
        }

        const float4 b0 = __ldg(reinterpret_cast<const float4*>(tp_bias) + lane);
        a0 += fdeg * b0.x; a1 += fdeg * b0.y; a2 += fdeg * b0.z; a3 += fdeg * b0.w;

        float s0 = a0 + a1 + a2 + a3;
        float q0 = a0 * a0 + a1 * a1 + a2 * a2 + a3 * a3;
        float q2 = 0.f;
#pragma unroll
        for (int i = 0; i < 12; i++) q2 += A[i] * A[i];
        s0 = warp_sum(s0); q0 = warp_sum(q0); q2 = warp_sum(q2);

        const float mu0 = s0 * (1.f / 128.f);
        const float r0  = rsqrtf(fmaxf(q0 * (1.f / 128.f) - mu0 * mu0, 0.f) + LN_EPS);
        const float r2  = rsqrtf(q2 * (1.f / 384.f) + LN_EPS);

        {   // field0
            const float4 wv = __ldg(reinterpret_cast<const float4*>(lnw) + lane);
            const float4 bv = __ldg(reinterpret_cast<const float4*>(lnb) + lane);
            float4 o;
            o.x = (a0 - mu0) * r0 * wv.x + bv.x;
            o.y = (a1 - mu0) * r0 * wv.y + bv.y;
            o.z = (a2 - mu0) * r0 * wv.z + bv.z;
            o.w = (a3 - mu0) * r0 * wv.w + bv.w;
            __stcs(reinterpret_cast<float4*>(row + 4 * lane), o);
        }
        {   // field2: channels u = 4*lane + {0..3}
            const float4 wv = __ldg(reinterpret_cast<const float4*>(lnw + 192) + lane);
            const float sa = wv.x * r2, sb = wv.y * r2, sc = wv.z * r2, sd = wv.w * r2;
            __stcs(reinterpret_cast<float4*>(row + 192 + 12 * lane),
                   make_float4(A[0] * sa, A[1] * sa, A[2]  * sa, A[3]  * sb));
            __stcs(reinterpret_cast<float4*>(row + 192 + 12 * lane + 4),
                   make_float4(A[4] * sb, A[5] * sb, A[6]  * sc, A[7]  * sc));
            __stcs(reinterpret_cast<float4*>(row + 192 + 12 * lane + 8),
                   make_float4(A[8] * sc, A[9] * sd, A[10] * sd, A[11] * sd));
        }
    } else {
        // ============ vector path: out0b (2) + out1b (6) + out1c (6) ==========
        float ob0 = 0.f, ob1 = 0.f;
        float B[6], C[6];
#pragma unroll
        for (int i = 0; i < 6; i++) { B[i] = 0.f; C[i] = 0.f; }

        int ei = 0;
        for (; ei + 1 < deg; ei += 2) {
            const int2 es0 = __ldg(bucket + ei);
            const int2 es1 = __ldg(bucket + ei + 1);

            const float4 sh0 = __ldg(reinterpret_cast<const float4*>(edge_sh) + es0.x);
            const float4 sh1 = __ldg(reinterpret_cast<const float4*>(edge_sh) + es1.x);
            const float* xr0 = node_feat + (size_t)es0.y * 320u + 128u;
            const float* xr1 = node_feat + (size_t)es1.y * 320u + 128u;
            const float* wr0 = edge_weight + (size_t)es0.x * 448u;
            const float* wr1 = edge_weight + (size_t)es1.x * 448u;

            const float2 w20 = __ldcs(reinterpret_cast<const float2*>(wr0 + 256) + lane);
            const float2 w30 = __ldcs(reinterpret_cast<const float2*>(wr0 + 320) + lane);
            const float2 w40 = __ldcs(reinterpret_cast<const float2*>(wr0 + 384) + lane);
            const float2 p00 = __ldg(reinterpret_cast<const float2*>(xr0 + 6 * lane));
            const float2 p10 = __ldg(reinterpret_cast<const float2*>(xr0 + 6 * lane + 2));
            const float2 p20 = __ldg(reinterpret_cast<const float2*>(xr0 + 6 * lane + 4));

            const float2 w21 = __ldcs(reinterpret_cast<const float2*>(wr1 + 256) + lane);
            const float2 w31 = __ldcs(reinterpret_cast<const float2*>(wr1 + 320) + lane);
            const float2 w41 = __ldcs(reinterpret_cast<const float2*>(wr1 + 384) + lane);
            const float2 p01 = __ldg(reinterpret_cast<const float2*>(xr1 + 6 * lane));
            const float2 p11 = __ldg(reinterpret_cast<const float2*>(xr1 + 6 * lane + 2));
            const float2 p21 = __ldg(reinterpret_cast<const float2*>(xr1 + 6 * lane + 4));

            {
                const float ys = sh0.x, yv0 = sh0.y, yv1 = sh0.z, yv2 = sh0.w;
                const float d0 = p00.x * yv0 + p00.y * yv1 + p10.x * yv2;
                const float d1 = p10.y * yv0 + p20.x * yv1 + p20.y * yv2;
                ob0 += w30.x * d0 * INV_SQRT3;
                ob1 += w30.y * d1 * INV_SQRT3;
                const float c0 = w20.x * ys, c1 = w20.y * ys;
                B[0] += c0 * p00.x; B[1] += c0 * p00.y; B[2] += c0 * p10.x;
                B[3] += c1 * p10.y; B[4] += c1 * p20.x; B[5] += c1 * p20.y;
                const float k0 = w40.x * INV_SQRT2, k1 = w40.y * INV_SQRT2;
                C[0] += k0 * (p00.y * yv2 - p10.x * yv1);
                C[1] += k0 * (p10.x * yv0 - p00.x * yv2);
                C[2] += k0 * (p00.x * yv1 - p00.y * yv0);
                C[3] += k1 * (p20.x * yv2 - p20.y * yv1);
                C[4] += k1 * (p20.y * yv0 - p10.y * yv2);
                C[5] += k1 * (p10.y * yv1 - p20.x * yv0);
            }
            {
                const float ys = sh1.x, yv0 = sh1.y, yv1 = sh1.z, yv2 = sh1.w;
                const float d0 = p01.x * yv0 + p01.y * yv1 + p11.x * yv2;
                const float d1 = p11.y * yv0 + p21.x * yv1 + p21.y * yv2;
                ob0 += w31.x * d0 * INV_SQRT3;
                ob1 += w31.y * d1 * INV_SQRT3;
                const float c0 = w21.x * ys, c1 = w21.y * ys;
                B[0] += c0 * p01.x; B[1] += c0 * p01.y; B[2] += c0 * p11.x;
                B[3] += c1 * p11.y; B[4] += c1 * p21.x; B[5] += c1 * p21.y;
                const float k0 = w41.x * INV_SQRT2, k1 = w41.y * INV_SQRT2;
                C[0] += k0 * (p01.y * yv2 - p11.x * yv1);
                C[1] += k0 * (p11.x * yv0 - p01.x * yv2);
                C[2] += k0 * (p01.x * yv1 - p01.y * yv0);
                C[3] += k1 * (p21.x * yv2 - p21.y * yv1);
                C[4] += k1 * (p21.y * yv0 - p11.y * yv2);
                C[5] += k1 * (p11.y * yv1 - p21.x * yv0);
            }
        }
        if (ei < deg) {
            const int2 es0 = __ldg(bucket + ei);
            const float4 sh0 = __ldg(reinterpret_cast<const float4*>(edge_sh) + es0.x);
            const float* xr0 = node_feat + (size_t)es0.y * 320u + 128u;
            const float* wr0 = edge_weight + (size_t)es0.x * 448u;
            const float2 w20 = __ldcs(reinterpret_cast<const float2*>(wr0 + 256) + lane);
            const float2 w30 = __ldcs(reinterpret_cast<const float2*>(wr0 + 320) + lane);
            const float2 w40 = __ldcs(reinterpret_cast<const float2*>(wr0 + 384) + lane);
            const float2 p00 = __ldg(reinterpret_cast<const float2*>(xr0 + 6 * lane));
            const float2 p10 = __ldg(reinterpret_cast<const float2*>(xr0 + 6 * lane + 2));
            const float2 p20 = __ldg(reinterpret_cast<const float2*>(xr0 + 6 * lane + 4));
            const float ys = sh0.x, yv0 = sh0.y, yv1 = sh0.z, yv2 = sh0.w;
            const float d0 = p00.x * yv0 + p00.y * yv1 + p10.x * yv2;
            const float d1 = p10.y * yv0 + p20.x * yv1 + p20.y * yv2;
            ob0 += w30.x * d0 * INV_SQRT3;
            ob1 += w30.y * d1 * INV_SQRT3;
            const float c0 = w20.x * ys, c1 = w20.y * ys;
            B[0] += c0 * p00.x; B[1] += c0 * p00.y; B[2] += c0 * p10.x;
            B[3] += c1 * p10.y; B[4] += c1 * p20.x; B[5] += c1 * p20.y;
            const float k0 = w40.x * INV_SQRT2, k1 = w40.y * INV_SQRT2;
            C[0] += k0 * (p00.y * yv2 - p10.x * yv1);
            C[1] += k0 * (p10.x * yv0 - p00.x * yv2);
            C[2] += k0 * (p00.x * yv1 - p00.y * yv0);
            C[3] += k1 * (p20.x * yv2 - p20.y * yv1);
            C[4] += k1 * (p20.y * yv0 - p10.y * yv2);
            C[5] += k1 * (p10.y * yv1 - p20.x * yv0);
        }

        const float2 bb = __ldg(reinterpret_cast<const float2*>(tp_bias + 128) + lane);
        ob0 += fdeg * bb.x; ob1 += fdeg * bb.y;

        float s1 = ob0 + ob1;
        float q1 = ob0 * ob0 + ob1 * ob1;
        float q3 = 0.f, q4 = 0.f;
#pragma unroll
        for (int i = 0; i < 6; i++) { q3 += B[i] * B[i]; q4 += C[i] * C[i]; }
        s1 = warp_sum(s1); q1 = warp_sum(q1);
        q3 = warp_sum(q3); q4 = warp_sum(q4);

        const float mu1 = s1 * (1.f / 64.f);
        const float r1  = rsqrtf(fmaxf(q1 * (1.f / 64.f) - mu1 * mu1, 0.f) + LN_EPS);
        const float r3  = rsqrtf(q3 * (1.f / 192.f) + LN_EPS);
        const float r4  = rsqrtf(q4 * (1.f / 192.f) + LN_EPS);

        {   // field1
            const float2 wv = __ldg(reinterpret_cast<const float2*>(lnw + 128) + lane);
            const float2 bv = __ldg(reinterpret_cast<const float2*>(lnb + 128) + lane);
            float2 o;
            o.x = (ob0 - mu1) * r1 * wv.x + bv.x;
            o.y = (ob1 - mu1) * r1 * wv.y + bv.y;
            __stcs(reinterpret_cast<float2*>(row + 128 + 2 * lane), o);
        }
        {   // field3
            const float2 wv = __ldg(reinterpret_cast<const float2*>(lnw + 320) + lane);
            const float sa = wv.x * r3, sb = wv.y * r3;
            __stcs(reinterpret_cast<float2*>(row + 576 + 6 * lane),     make_float2(B[0] * sa, B[1] * sa));
            __stcs(reinterpret_cast<float2*>(row + 576 + 6 * lane + 2), make_float2(B[2] * sa, B[3] * sb));
            __stcs(reinterpret_cast<float2*>(row + 576 + 6 * lane + 4), make_float2(B[4] * sb, B[5] * sb));
        }
        {   // field4
            const float2 wv = __ldg(reinterpret_cast<const float2*>(lnw + 384) + lane);
            const float sa = wv.x * r4, sb = wv.y * r4;
            __stcs(reinterpret_cast<float2*>(row + 768 + 6 * lane),     make_float2(C[0] * sa, C[1] * sa));
            __stcs(reinterpret_cast<float2*>(row + 768 + 6 * lane + 2), make_float2(C[2] * sa, C[3] * sb));
            __stcs(reinterpret_cast<float2*>(row + 768 + 6 * lane + 4), make_float2(C[4] * sb, C[5] * sb));
        }
    }
}

// ---------------------------------------------------------------------------
extern "C" void kernel_launch(void* const* d_in, const int* in_sizes, int n_in,
                              void* d_out, int out_size)
{
    const float* node_feat   = (const float*)d_in[0];
    const float* edge_sh     = (const float*)d_in[1];
    const float* edge_weight = (const float*)d_in[2];
    const float* tp_bias     = (const float*)d_in[3];
    const float* ln_weight   = (const float*)d_in[4];
    const float* ln_bias     = (const float*)d_in[5];
    const int*   edge_src    = (const int*)d_in[6];
    const int*   edge_dst    = (const int*)d_in[7];
    float* out = (float*)d_out;

    const int n_nodes = in_sizes[0] / 320;
    const int n_edges = in_sizes[7];

    // single-pass bucketing, 1 edge per thread
    bucket_kernel<<<(n_edges + 255) / 256, 256>>>(edge_dst, edge_src, n_edges);

    // deg snapshot + hist re-zero (restores entry invariant)
    {
        const int threads = (n_nodes + 3) / 4;
        deg_kernel<<<(threads + 255) / 256, 256>>>(n_nodes);
    }

    // 2 warps per node (channel-split), 2 nodes per 128-thread block
    const int blocks = (n_nodes + 1) / 2;
    fused_tp_ln_kernel<<<blocks, 128>>>(node_feat, edge_sh, edge_weight,
                                        tp_bias, ln_weight, ln_bias,
                                        out, n_nodes);
}

// round 17
// speedup vs baseline: 1.4758x; 1.0073x over previous
#include <cuda_runtime.h>
#include <cuda_bf16.h>
#include <cstdint>

#define INV_SQRT3 0.57735026918962576451f
#define INV_SQRT2 0.70710678118654752440f
#define LN_EPS 1e-5f

#define MAX_NODES 16384
#define MAX_EDGES 131072
#define BUCKET_CAP 64   // max degree ~27 for Poisson(8); 64 is >>10 sigma

// scratch (allocation-free rule: __device__ globals; statically zero-initialized)
__device__ int  g_hist[MAX_NODES];                     // ALWAYS zero at kernel_launch entry
__device__ int  g_deg[MAX_NODES];
__device__ int2 g_bucket[MAX_NODES * BUCKET_CAP];      // (edge_id, src_node) per dst bucket

__device__ __forceinline__ float warp_sum(float v) {
    v += __shfl_xor_sync(0xffffffffu, v, 16);
    v += __shfl_xor_sync(0xffffffffu, v, 8);
    v += __shfl_xor_sync(0xffffffffu, v, 4);
    v += __shfl_xor_sync(0xffffffffu, v, 2);
    v += __shfl_xor_sync(0xffffffffu, v, 1);
    return v;
}

// ---------------------------------------------------------------------------
// Single-pass bucketing: 1 edge per thread.
// ---------------------------------------------------------------------------
__global__ void bucket_kernel(const int* __restrict__ edge_dst,
                              const int* __restrict__ edge_src,
                              int n_edges) {
    const int i = blockIdx.x * blockDim.x + threadIdx.x;
    if (i < n_edges) {
        const int dd = __ldg(edge_dst + i);
        const int ss = __ldg(edge_src + i);
        const int r = atomicAdd(&g_hist[dd], 1);
        if (r < BUCKET_CAP) g_bucket[dd * BUCKET_CAP + r] = make_int2(i, ss);
    }
}

// copy hist -> deg (clamped) and restore the g_hist zero-invariant.
__global__ void deg_kernel(int n_nodes) {
    const int i4 = (blockIdx.x * blockDim.x + threadIdx.x) * 4;
    if (i4 + 3 < n_nodes) {
        int4 h = *reinterpret_cast<const int4*>(g_hist + i4);
        h.x = min(h.x, BUCKET_CAP); h.y = min(h.y, BUCKET_CAP);
        h.z = min(h.z, BUCKET_CAP); h.w = min(h.w, BUCKET_CAP);
        *reinterpret_cast<int4*>(g_deg + i4) = h;
        *reinterpret_cast<int4*>(g_hist + i4) = make_int4(0, 0, 0, 0);
    } else {
        for (int i = i4; i < n_nodes; i++) {
            g_deg[i] = min(g_hist[i], BUCKET_CAP);
            g_hist[i] = 0;
        }
    }
}

// ---------------------------------------------------------------------------
// Fused gather + depthwise TP + bias + equivariant LN.
// TWO warps per node, split by CHANNEL GROUP (fully independent):
//   sub 0 (scalar path): xs,w0,w1  -> fields 0 (out0a), 2 (out1a)
//   sub 1 (vector path): xv,w2..w4 -> fields 1, 3, 4
// 64-thread blocks = 1 node per block: finest work-stealing granularity,
// minimal straggler tail. 16 blocks/SM keeps 32 warps/SM at <=64 regs.
// edge_weight via __ldcs, outputs via __stcs.
// ---------------------------------------------------------------------------
__global__ void __launch_bounds__(64, 16) fused_tp_ln_kernel(
    const float* __restrict__ node_feat,   // (N, 320)
    const float* __restrict__ edge_sh,     // (E, 4)
    const float* __restrict__ edge_weight, // (E, 448)
    const float* __restrict__ tp_bias,     // (192,)
    const float* __restrict__ lnw,         // (448,)
    const float* __restrict__ lnb,         // (192,)
    float*       __restrict__ out,         // (N, 960)
    int n_nodes)
{
    const int lane = threadIdx.x & 31;
    const int sub  = threadIdx.x >> 5;     // 0 or 1
    const int node = blockIdx.x;
    if (node >= n_nodes) return;

    const int deg = __ldg(g_deg + node);
    const float fdeg = (float)deg;
    const int2* bucket = g_bucket + (size_t)node * BUCKET_CAP;

    float* row = out + (size_t)node * 960u;

    if (sub == 0) {
        // ================= scalar path: out0a (4) + out1a (12) ================
        float a0 = 0.f, a1 = 0.f, a2 = 0.f, a3 = 0.f;
        float A[12];
#pragma unroll
        for (int i = 0; i < 12; i++) A[i] = 0.f;

        int ei = 0;
        for (; ei + 1 < deg; ei += 2) {
            const int2 es0 = __ldg(bucket + ei);
            const int2 es1 = __ldg(bucket + ei + 1);

            const float4 sh0 = __ldg(reinterpret_cast<const float4*>(edge_sh) + es0.x);
            const float4 sh1 = __ldg(reinterpret_cast<const float4*>(edge_sh) + es1.x);
            const float4 xs0 = __ldg(reinterpret_cast<const float4*>(node_feat + (size_t)es0.y * 320u) + lane);
            const float4 xs1 = __ldg(reinterpret_cast<const float4*>(node_feat + (size_t)es1.y * 320u) + lane);
            const float* wr0 = edge_weight + (size_t)es0.x * 448u;
            const float* wr1 = edge_weight + (size_t)es1.x * 448u;
            const float4 w00 = __ldcs(reinterpret_cast<const float4*>(wr0) + lane);
            const float4 w01 = __ldcs(reinterpret_cast<const float4*>(wr1) + lane);
            const float4 w10 = __ldcs(reinterpret_cast<const float4*>(wr0 + 128) + lane);
            const float4 w11 = __ldcs(reinterpret_cast<const float4*>(wr1 + 128) + lane);

            {
                const float ys = sh0.x;
                a0 += w00.x * xs0.x * ys; a1 += w00.y * xs0.y * ys;
                a2 += w00.z * xs0.z * ys; a3 += w00.w * xs0.w * ys;
                const float t0 = w10.x * xs0.x, t1 = w10.y * xs0.y;
                const float t2 = w10.z * xs0.z, t3 = w10.w * xs0.w;
                A[0] += t0 * sh0.y; A[1]  += t0 * sh0.z; A[2]  += t0 * sh0.w;
                A[3] += t1 * sh0.y; A[4]  += t1 * sh0.z; A[5]  += t1 * sh0.w;
                A[6] += t2 * sh0.y; A[7]  += t2 * sh0.z; A[8]  += t2 * sh0.w;
                A[9] += t3 * sh0.y; A[10] += t3 * sh0.z; A[11] += t3 * sh0.w;
            }
            {
                const float ys = sh1.x;
                a0 += w01.x * xs1.x * ys; a1 += w01.y * xs1.y * ys;
                a2 += w01.z * xs1.z * ys; a3 += w01.w * xs1.w * ys;
                const float t0 = w11.x * xs1.x, t1 = w11.y * xs1.y;
                const float t2 = w11.z * xs1.z, t3 = w11.w * xs1.w;
                A[0] += t0 * sh1.y; A[1]  += t0 * sh1.z; A[2]  += t0 * sh1.w;
                A[3] += t1 * sh1.y; A[4]  += t1 * sh1.z; A[5]  += t1 * sh1.w;
                A[6] += t2 * sh1.y; A[7]  += t2 * sh1.z; A[8]  += t2 * sh1.w;
                A[9] += t3 * sh1.y; A[10] += t3 * sh1.z; A[11] += t3 * sh1.w;
            }
        }
        if (ei < deg) {
            const int2 es0 = __ldg(bucket + ei);
            const float4 sh0 = __ldg(reinterpret_cast<const float4*>(edge_sh) + es0.x);
            const float4 xs0 = __ldg(reinterpret_cast<const float4*>(node_feat + (size_t)es0.y * 320u) + lane);
            const float* wr0 = edge_weight + (size_t)es0.x * 448u;
            const float4 w00 = __ldcs(reinterpret_cast<const float4*>(wr0) + lane);
            const float4 w10 = __ldcs(reinterpret_cast<const float4*>(wr0 + 128) + lane);
            const float ys = sh0.x;
            a0 += w00.x * xs0.x * ys; a1 += w00.y * xs0.y * ys;
            a2 += w00.z * xs0.z * ys; a3 += w00.w * xs0.w * ys;
            const float t0 = w10.x * xs0.x, t1 = w10.y * xs0.y;
            const float t2 = w10.z * xs0.z, t3 = w10.w * xs0.w;
            A[0] += t0 * sh0.y; A[1]  += t0 * sh0.z; A[2]  += t0 * sh0.w;
            A[3] += t1 * sh0.y; A[4]  += t1 * sh0.z; A[5]  += t1 * sh0.w;
            A[6] += t2 * sh0.y; A[7]  += t2 * sh0.z; A[8]  += t2 * sh0.w;
            A[9] += t3 * sh0.y; A[10] += t3 * sh0.z; A[11] += t3 * sh0.w;
        }

        const float4 b0 = __ldg(reinterpret_cast<const float4*>(tp_bias) + lane);
        a0 += fdeg * b0.x; a1 += fdeg * b0.y; a2 += fdeg * b0.z; a3 += fdeg * b0.w;

        float s0 = a0 + a1 + a2 + a3;
        float q0 = a0 * a0 + a1 * a1 + a2 * a2 + a3 * a3;
        float q2 = 0.f;
#pragma unroll
        for (int i = 0; i < 12; i++) q2 += A[i] * A[i];
        s0 = warp_sum(s0); q0 = warp_sum(q0); q2 = warp_sum(q2);

        const float mu0 = s0 * (1.f / 128.f);
        const float r0  = rsqrtf(fmaxf(q0 * (1.f / 128.f) - mu0 * mu0, 0.f) + LN_EPS);
        const float r2  = rsqrtf(q2 * (1.f / 384.f) + LN_EPS);

        {   // field0
            const float4 wv = __ldg(reinterpret_cast<const float4*>(lnw) + lane);
            const float4 bv = __ldg(reinterpret_cast<const float4*>(lnb) + lane);
            float4 o;
            o.x = (a0 - mu0) * r0 * wv.x + bv.x;
            o.y = (a1 - mu0) * r0 * wv.y + bv.y;
            o.z = (a2 - mu0) * r0 * wv.z + bv.z;
            o.w = (a3 - mu0) * r0 * wv.w + bv.w;
            __stcs(reinterpret_cast<float4*>(row + 4 * lane), o);
        }
        {   // field2: channels u = 4*lane + {0..3}
            const float4 wv = __ldg(reinterpret_cast<const float4*>(lnw + 192) + lane);
            const float sa = wv.x * r2, sb = wv.y * r2, sc = wv.z * r2, sd = wv.w * r2;
            __stcs(reinterpret_cast<float4*>(row + 192 + 12 * lane),
                   make_float4(A[0] * sa, A[1] * sa, A[2]  * sa, A[3]  * sb));
            __stcs(reinterpret_cast<float4*>(row + 192 + 12 * lane + 4),
                   make_float4(A[4] * sb, A[5] * sb, A[6]  * sc, A[7]  * sc));
            __stcs(reinterpret_cast<float4*>(row + 192 + 12 * lane + 8),
                   make_float4(A[8] * sc, A[9] * sd, A[10] * sd, A[11] * sd));
        }
    } else {
        // ============ vector path: out0b (2) + out1b (6) + out1c (6) ==========
        float ob0 = 0.f, ob1 = 0.f;
        float B[6], C[6];
#pragma unroll
        for (int i = 0; i < 6; i++) { B[i] = 0.f; C[i] = 0.f; }

        int ei = 0;
        for (; ei + 1 < deg; ei += 2) {
            const int2 es0 = __ldg(bucket + ei);
            const int2 es1 = __ldg(bucket + ei + 1);

            const float4 sh0 = __ldg(reinterpret_cast<const float4*>(edge_sh) + es0.x);
            const float4 sh1 = __ldg(reinterpret_cast<const float4*>(edge_sh) + es1.x);
            const float* xr0 = node_feat + (size_t)es0.y * 320u + 128u;
            const float* xr1 = node_feat + (size_t)es1.y * 320u + 128u;
            const float* wr0 = edge_weight + (size_t)es0.x * 448u;
            const float* wr1 = edge_weight + (size_t)es1.x * 448u;

            const float2 w20 = __ldcs(reinterpret_cast<const float2*>(wr0 + 256) + lane);
            const float2 w30 = __ldcs(reinterpret_cast<const float2*>(wr0 + 320) + lane);
            const float2 w40 = __ldcs(reinterpret_cast<const float2*>(wr0 + 384) + lane);
            const float2 p00 = __ldg(reinterpret_cast<const float2*>(xr0 + 6 * lane));
            const float2 p10 = __ldg(reinterpret_cast<const float2*>(xr0 + 6 * lane + 2));
            const float2 p20 = __ldg(reinterpret_cast<const float2*>(xr0 + 6 * lane + 4));

            const float2 w21 = __ldcs(reinterpret_cast<const float2*>(wr1 + 256) + lane);
            const float2 w31 = __ldcs(reinterpret_cast<const float2*>(wr1 + 320) + lane);
            const float2 w41 = __ldcs(reinterpret_cast<const float2*>(wr1 + 384) + lane);
            const float2 p01 = __ldg(reinterpret_cast<const float2*>(xr1 + 6 * lane));
            const float2 p11 = __ldg(reinterpret_cast<const float2*>(xr1 + 6 * lane + 2));
            const float2 p21 = __ldg(reinterpret_cast<const float2*>(xr1 + 6 * lane + 4));

            {
                const float ys = sh0.x, yv0 = sh0.y, yv1 = sh0.z, yv2 = sh0.w;
                const float d0 = p00.x * yv0 + p00.y * yv1 + p10.x * yv2;
                const float d1 = p10.y * yv0 + p20.x * yv1 + p20.y * yv2;
                ob0 += w30.x * d0 * INV_SQRT3;
                ob1 += w30.y * d1 * INV_SQRT3;
                const float c0 = w20.x * ys, c1 = w20.y * ys;
                B[0] += c0 * p00.x; B[1] += c0 * p00.y; B[2] += c0 * p10.x;
                B[3] += c1 * p10.y; B[4] += c1 * p20.x; B[5] += c1 * p20.y;
                const float k0 = w40.x * INV_SQRT2, k1 = w40.y * INV_SQRT2;
                C[0] += k0 * (p00.y * yv2 - p10.x * yv1);
                C[1] += k0 * (p10.x * yv0 - p00.x * yv2);
                C[2] += k0 * (p00.x * yv1 - p00.y * yv0);
                C[3] += k1 * (p20.x * yv2 - p20.y * yv1);
                C[4] += k1 * (p20.y * yv0 - p10.y * yv2);
                C[5] += k1 * (p10.y * yv1 - p20.x * yv0);
            }
            {
                const float ys = sh1.x, yv0 = sh1.y, yv1 = sh1.z, yv2 = sh1.w;
                const float d0 = p01.x * yv0 + p01.y * yv1 + p11.x * yv2;
                const float d1 = p11.y * yv0 + p21.x * yv1 + p21.y * yv2;
                ob0 += w31.x * d0 * INV_SQRT3;
                ob1 += w31.y * d1 * INV_SQRT3;
                const float c0 = w21.x * ys, c1 = w21.y * ys;
                B[0] += c0 * p01.x; B[1] += c0 * p01.y; B[2] += c0 * p11.x;
                B[3] += c1 * p11.y; B[4] += c1 * p21.x; B[5] += c1 * p21.y;
                const float k0 = w41.x * INV_SQRT2, k1 = w41.y * INV_SQRT2;
                C[0] += k0 * (p01.y * yv2 - p11.x * yv1);
                C[1] += k0 * (p11.x * yv0 - p01.x * yv2);
                C[2] += k0 * (p01.x * yv1 - p01.y * yv0);
                C[3] += k1 * (p21.x * yv2 - p21.y * yv1);
                C[4] += k1 * (p21.y * yv0 - p11.y * yv2);
                C[5] += k1 * (p11.y * yv1 - p21.x * yv0);
            }
        }
        if (ei < deg) {
            const int2 es0 = __ldg(bucket + ei);
            const float4 sh0 = __ldg(reinterpret_cast<const float4*>(edge_sh) + es0.x);
            const float* xr0 = node_feat + (size_t)es0.y * 320u + 128u;
            const float* wr0 = edge_weight + (size_t)es0.x * 448u;
            const float2 w20 = __ldcs(reinterpret_cast<const float2*>(wr0 + 256) + lane);
            const float2 w30 = __ldcs(reinterpret_cast<const float2*>(wr0 + 320) + lane);
            const float2 w40 = __ldcs(reinterpret_cast<const float2*>(wr0 + 384) + lane);
            const float2 p00 = __ldg(reinterpret_cast<const float2*>(xr0 + 6 * lane));
            const float2 p10 = __ldg(reinterpret_cast<const float2*>(xr0 + 6 * lane + 2));
            const float2 p20 = __ldg(reinterpret_cast<const float2*>(xr0 + 6 * lane + 4));
            const float ys = sh0.x, yv0 = sh0.y, yv1 = sh0.z, yv2 = sh0.w;
            const float d0 = p00.x * yv0 + p00.y * yv1 + p10.x * yv2;
            const float d1 = p10.y * yv0 + p20.x * yv1 + p20.y * yv2;
            ob0 += w30.x * d0 * INV_SQRT3;
            ob1 += w30.y * d1 * INV_SQRT3;
            const float c0 = w20.x * ys, c1 = w20.y * ys;
            B[0] += c0 * p00.x; B[1] += c0 * p00.y; B[2] += c0 * p10.x;
            B[3] += c1 * p10.y; B[4] += c1 * p20.x; B[5] += c1 * p20.y;
            const float k0 = w40.x * INV_SQRT2, k1 = w40.y * INV_SQRT2;
            C[0] += k0 * (p00.y * yv2 - p10.x * yv1);
            C[1] += k0 * (p10.x * yv0 - p00.x * yv2);
            C[2] += k0 * (p00.x * yv1 - p00.y * yv0);
            C[3] += k1 * (p20.x * yv2 - p20.y * yv1);
            C[4] += k1 * (p20.y * yv0 - p10.y * yv2);
            C[5] += k1 * (p10.y * yv1 - p20.x * yv0);
        }

        const float2 bb = __ldg(reinterpret_cast<const float2*>(tp_bias + 128) + lane);
        ob0 += fdeg * bb.x; ob1 += fdeg * bb.y;

        float s1 = ob0 + ob1;
        float q1 = ob0 * ob0 + ob1 * ob1;
        float q3 = 0.f, q4 = 0.f;
#pragma unroll
        for (int i = 0; i < 6; i++) { q3 += B[i] * B[i]; q4 += C[i] * C[i]; }
        s1 = warp_sum(s1); q1 = warp_sum(q1);
        q3 = warp_sum(q3); q4 = warp_sum(q4);

        const float mu1 = s1 * (1.f / 64.f);
        const float r1  = rsqrtf(fmaxf(q1 * (1.f / 64.f) - mu1 * mu1, 0.f) + LN_EPS);
        const float r3  = rsqrtf(q3 * (1.f / 192.f) + LN_EPS);
        const float r4  = rsqrtf(q4 * (1.f / 192.f) + LN_EPS);

        {   // field1
            const float2 wv = __ldg(reinterpret_cast<const float2*>(lnw + 128) + lane);
            const float2 bv = __ldg(reinterpret_cast<const float2*>(lnb + 128) + lane);
            float2 o;
            o.x = (ob0 - mu1) * r1 * wv.x + bv.x;
            o.y = (ob1 - mu1) * r1 * wv.y + bv.y;
            __stcs(reinterpret_cast<float2*>(row + 128 + 2 * lane), o);
        }
        {   // field3
            const float2 wv = __ldg(reinterpret_cast<const float2*>(lnw + 320) + lane);
            const float sa = wv.x * r3, sb = wv.y * r3;
            __stcs(reinterpret_cast<float2*>(row + 576 + 6 * lane),     make_float2(B[0] * sa, B[1] * sa));
            __stcs(reinterpret_cast<float2*>(row + 576 + 6 * lane + 2), make_float2(B[2] * sa, B[3] * sb));
            __stcs(reinterpret_cast<float2*>(row + 576 + 6 * lane + 4), make_float2(B[4] * sb, B[5] * sb));
        }
        {   // field4
            const float2 wv = __ldg(reinterpret_cast<const float2*>(lnw + 384) + lane);
            const float sa = wv.x * r4, sb = wv.y * r4;
            __stcs(reinterpret_cast<float2*>(row + 768 + 6 * lane),     make_float2(C[0] * sa, C[1] * sa));
            __stcs(reinterpret_cast<float2*>(row + 768 + 6 * lane + 2), make_float2(C[2] * sa, C[3] * sb));
            __stcs(reinterpret_cast<float2*>(row + 768 + 6 * lane + 4), make_float2(C[4] * sb, C[5] * sb));
        }
    }
}

// ---------------------------------------------------------------------------
extern "C" void kernel_launch(void* const* d_in, const int* in_sizes, int n_in,
                              void* d_out, int out_size)
{
    const float* node_feat   = (const float*)d_in[0];
    const float* edge_sh     = (const float*)d_in[1];
    const float* edge_weight = (const float*)d_in[2];
    const float* tp_bias     = (const float*)d_in[3];
    const float* ln_weight   = (const float*)d_in[4];
    const float* ln_bias     = (const float*)d_in[5];
    const int*   edge_src    = (const int*)d_in[6];
    const int*   edge_dst    = (const int*)d_in[7];
    float* out = (float*)d_out;

    const int n_nodes = in_sizes[0] / 320;
    const int n_edges = in_sizes[7];

    // single-pass bucketing, 1 edge per thread
    bucket_kernel<<<(n_edges + 255) / 256, 256>>>(edge_dst, edge_src, n_edges);

    // deg snapshot + hist re-zero (restores entry invariant)
    {
        const int threads = (n_nodes + 3) / 4;
        deg_kernel<<<(threads + 255) / 256, 256>>>(n_nodes);
    }

    // 2 warps per node (channel-split), 1 node per 64-thread block
    fused_tp_ln_kernel<<<n_nodes, 64>>>(node_feat, edge_sh, edge_weight,
                                        tp_bias, ln_weight, ln_bias,
                                        out, n_nodes);
}